// round 7
// baseline (speedup 1.0000x reference)
#include <cuda_runtime.h>
#include <cuda_bf16.h>
#include <cstdint>
#include <math.h>

#define BB 128
#define DD 128
#define QQ 256
#define LL 1024
#define TEMP 4.0f

#define QUERY_ELEMS ((size_t)BB * DD * QQ)   // 4,194,304
#define WC_ELEMS    ((size_t)BB * DD * QQ)   // 4,194,304
#define AMAP_ELEMS  ((size_t)BB * QQ * LL)   // 33,554,432

__device__ __align__(16) float g_attn_q[(size_t)BB * LL * QQ];   // 134 MB
__device__ __align__(16) float g_scratch_amap[AMAP_ELEMS];       // fallback
__device__ __align__(16) float g_scratch_wc[WC_ELEMS];           // fallback

// ============================ helpers ======================================
__device__ __forceinline__ uint32_t smem_u32(const void* p) {
    uint32_t a;
    asm("{ .reg .u64 t; cvta.to.shared.u64 t, %1; cvt.u32.u64 %0, t; }"
        : "=r"(a) : "l"(p));
    return a;
}
__device__ __forceinline__ uint32_t pack2bf(float x, float y) {
    __nv_bfloat162 h = __floats2bfloat162_rn(x, y);
    return *(uint32_t*)&h;
}
__device__ __forceinline__ void split2(float x, float y,
                                       uint32_t& hi, uint32_t& lo) {
    __nv_bfloat16 hx = __float2bfloat16_rn(x);
    __nv_bfloat16 hy = __float2bfloat16_rn(y);
    float rx = x - __bfloat162float(hx);
    float ry = y - __bfloat162float(hy);
    __nv_bfloat162 h2; h2.x = hx; h2.y = hy;
    hi = *(uint32_t*)&h2;
    lo = pack2bf(rx, ry);
}
#define LDMATRIX_X4(r0, r1, r2, r3, addr) \
    asm volatile("ldmatrix.sync.aligned.m8n8.x4.shared.b16 {%0,%1,%2,%3}, [%4];" \
                 : "=r"(r0), "=r"(r1), "=r"(r2), "=r"(r3) : "r"(addr))
#define MMA_BF16(c, a0, a1, a2, a3, b0, b1) \
    asm volatile("mma.sync.aligned.m16n8k16.row.col.f32.bf16.bf16.f32 " \
                 "{%0,%1,%2,%3}, {%4,%5,%6,%7}, {%8,%9}, {%0,%1,%2,%3};" \
                 : "+f"((c)[0]), "+f"((c)[1]), "+f"((c)[2]), "+f"((c)[3]) \
                 : "r"(a0), "r"(a1), "r"(a2), "r"(a3), "r"(b0), "r"(b1))

// u32-index swizzle for K-major bf16-pair tiles (row = M/N index, col = u32 0..63)
__device__ __forceinline__ int swz(int row, int col) {
    return row * 64 + ((((col >> 2) ^ (row & 7)) << 2) | (col & 3));
}

// ---------------------------------------------------------------------------
// Kernel 1 (HMMA bf16 split): scores = ctx^T @ query, fused softmax over Q.
// CTA: M=64(l) x N=256(q), K=128(d) fully resident. grid (16, B), block 256.
// smem u32 layout: AHI[64*64] ALO[64*64] BHI[256*64] BLO[256*64] = 160 KB.
// Epilogue reuses smem as scores[64][264] fp32.
// ---------------------------------------------------------------------------
#define K1_AHI 0
#define K1_ALO 4096
#define K1_BHI 8192
#define K1_BLO 24576
#define K1_SMEM_BYTES (40960 * 4)   // 160 KB

__global__ __launch_bounds__(256, 1)
void k1_mma(const float* __restrict__ query,
            const float* __restrict__ ctx) {
    extern __shared__ __align__(16) uint32_t sm1u[];
    const uint32_t sb = smem_u32(sm1u);

    const int tid  = threadIdx.x;
    const int lane = tid & 31;
    const int wid  = tid >> 5;
    const int wm   = wid & 1;        // 0..1 : 32 l-rows each
    const int wn   = wid >> 1;       // 0..3 : 64 q-cols each

    const int b  = blockIdx.y;
    const int l0 = blockIdx.x * 64;

    const float* ctxb = ctx + (size_t)b * DD * LL;
    const float* qb   = query + (size_t)b * DD * QQ;

    // ---- fill A: 64 l x 128 d  (transpose + split). 1024 units, 4/thread ----
    #pragma unroll
    for (int t = 0; t < 4; t++) {
        int u  = t * 256 + tid;
        int lu = u & 15;             // l-group (4 l each)
        int du = u >> 4;             // d-pair 0..63
        int l  = lu * 4;
        int d  = du * 2;
        float4 v0 = *(const float4*)(ctxb + (size_t)d * LL + l0 + l);
        float4 v1 = *(const float4*)(ctxb + (size_t)(d + 1) * LL + l0 + l);
        const float a0[4] = {v0.x, v0.y, v0.z, v0.w};
        const float a1[4] = {v1.x, v1.y, v1.z, v1.w};
        #pragma unroll
        for (int j = 0; j < 4; j++) {
            uint32_t hi, lo;
            split2(a0[j], a1[j], hi, lo);
            int o = swz(l + j, du);
            sm1u[K1_AHI + o] = hi;
            sm1u[K1_ALO + o] = lo;
        }
    }
    // ---- fill B: 256 q x 128 d (transpose + split). 4096 units, 16/thread ----
    #pragma unroll
    for (int t = 0; t < 16; t++) {
        int u  = t * 256 + tid;
        int qu = u & 63;             // q-group (4 q each)
        int du = u >> 6;             // d-pair 0..63
        int q  = qu * 4;
        int d  = du * 2;
        float4 v0 = *(const float4*)(qb + (size_t)d * QQ + q);
        float4 v1 = *(const float4*)(qb + (size_t)(d + 1) * QQ + q);
        const float b0[4] = {v0.x, v0.y, v0.z, v0.w};
        const float b1[4] = {v1.x, v1.y, v1.z, v1.w};
        #pragma unroll
        for (int j = 0; j < 4; j++) {
            uint32_t hi, lo;
            split2(b0[j], b1[j], hi, lo);
            int o = swz(q + j, du);
            sm1u[K1_BHI + o] = hi;
            sm1u[K1_BLO + o] = lo;
        }
    }
    __syncthreads();

    float acc[2][8][4];
    #pragma unroll
    for (int i = 0; i < 2; i++)
        #pragma unroll
        for (int j = 0; j < 8; j++)
            #pragma unroll
            for (int k = 0; k < 4; k++) acc[i][j][k] = 0.0f;

    // ---- MMA: 8 k16 steps x 3 split passes ----
    #pragma unroll
    for (int ks = 0; ks < 8; ks++) {
        uint32_t ah[2][4], al[2][4];
        #pragma unroll
        for (int mt = 0; mt < 2; mt++) {
            int row = wm * 32 + mt * 16 + (lane & 15);
            int ch  = 2 * ks + (lane >> 4);
            uint32_t off = (uint32_t)(row * 256 + ((ch ^ (row & 7)) << 4));
            LDMATRIX_X4(ah[mt][0], ah[mt][1], ah[mt][2], ah[mt][3],
                        sb + K1_AHI * 4 + off);
            LDMATRIX_X4(al[mt][0], al[mt][1], al[mt][2], al[mt][3],
                        sb + K1_ALO * 4 + off);
        }
        #pragma unroll
        for (int p = 0; p < 4; p++) {            // 2 n8-tiles per p
            int row = wn * 64 + p * 16 + ((lane >> 4) << 3) + (lane & 7);
            int ch  = 2 * ks + ((lane >> 3) & 1);
            uint32_t off = (uint32_t)(row * 256 + ((ch ^ (row & 7)) << 4));
            uint32_t bh0, bh1, bh2, bh3, bl0, bl1, bl2, bl3;
            LDMATRIX_X4(bh0, bh1, bh2, bh3, sb + K1_BHI * 4 + off);
            LDMATRIX_X4(bl0, bl1, bl2, bl3, sb + K1_BLO * 4 + off);
            #pragma unroll
            for (int mt = 0; mt < 2; mt++) {
                MMA_BF16(acc[mt][p * 2],     ah[mt][0], ah[mt][1], ah[mt][2], ah[mt][3], bh0, bh1);
                MMA_BF16(acc[mt][p * 2 + 1], ah[mt][0], ah[mt][1], ah[mt][2], ah[mt][3], bh2, bh3);
                MMA_BF16(acc[mt][p * 2],     ah[mt][0], ah[mt][1], ah[mt][2], ah[mt][3], bl0, bl1);
                MMA_BF16(acc[mt][p * 2 + 1], ah[mt][0], ah[mt][1], ah[mt][2], ah[mt][3], bl2, bl3);
                MMA_BF16(acc[mt][p * 2],     al[mt][0], al[mt][1], al[mt][2], al[mt][3], bh0, bh1);
                MMA_BF16(acc[mt][p * 2 + 1], al[mt][0], al[mt][1], al[mt][2], al[mt][3], bh2, bh3);
            }
        }
    }
    __syncthreads();   // smem A/B dead; reuse as scores

    // ---- scores to smem: 64 rows x 264 fp32 ----
    float* sc = (float*)sm1u;
    const int gid = lane >> 2;
    const int tig = lane & 3;
    #pragma unroll
    for (int mt = 0; mt < 2; mt++) {
        int r0 = wm * 32 + mt * 16 + gid;
        #pragma unroll
        for (int nt = 0; nt < 8; nt++) {
            int q = wn * 64 + nt * 8 + tig * 2;
            *(float2*)(sc + (size_t)r0 * 264 + q) =
                make_float2(acc[mt][nt][0], acc[mt][nt][1]);
            *(float2*)(sc + (size_t)(r0 + 8) * 264 + q) =
                make_float2(acc[mt][nt][2], acc[mt][nt][3]);
        }
    }
    __syncthreads();

    // ---- fused softmax over Q: warp wid owns rows wid*8..+7 ----
    const size_t outb = ((size_t)b * LL + l0 + wid * 8) * QQ;
    #pragma unroll
    for (int i = 0; i < 8; i++) {
        const float* row = sc + (size_t)(wid * 8 + i) * 264;
        float e[8];
        float m = -1e30f;
        #pragma unroll
        for (int j = 0; j < 8; j++) { e[j] = row[lane + j * 32]; m = fmaxf(m, e[j]); }
        #pragma unroll
        for (int o = 16; o; o >>= 1) m = fmaxf(m, __shfl_xor_sync(0xffffffffu, m, o));
        float s = 0.0f;
        #pragma unroll
        for (int j = 0; j < 8; j++) { e[j] = __expf(e[j] - m); s += e[j]; }
        #pragma unroll
        for (int o = 16; o; o >>= 1) s += __shfl_xor_sync(0xffffffffu, s, o);
        float inv = 1.0f / s;
        #pragma unroll
        for (int j = 0; j < 8; j++)
            g_attn_q[outb + (size_t)i * QQ + lane + j * 32] = e[j] * inv;
    }
}

// ---------------------------------------------------------------------------
// Kernel 3: attn_c[b,q,l] = softmax_l(TEMP * attn_q[b,l,q]). (unchanged)
// ---------------------------------------------------------------------------
__global__ void k3_softmax_l(float* __restrict__ amap) {
    extern __shared__ float sm3[];

    const int tid  = threadIdx.x;
    const int b    = blockIdx.y;
    const int q0   = blockIdx.x * 32;
    const int w    = tid >> 5;
    const int lane = tid & 31;

    const float* src = g_attn_q + (size_t)b * LL * QQ + q0;
    #pragma unroll
    for (int i = 0; i < 32; i++) {
        int l = i * 32 + w;
        sm3[lane * 1025 + l] = src[(size_t)l * QQ + lane];
    }
    __syncthreads();

    const float* row = sm3 + w * 1025;
    float e[32];
    float mx = -1e30f;
    #pragma unroll
    for (int i = 0; i < 32; i++) {
        float v = TEMP * row[lane + 32 * i];
        e[i] = v;
        mx = fmaxf(mx, v);
    }
    #pragma unroll
    for (int o = 16; o; o >>= 1) mx = fmaxf(mx, __shfl_xor_sync(0xffffffffu, mx, o));

    float s = 0.0f;
    #pragma unroll
    for (int i = 0; i < 32; i++) { e[i] = __expf(e[i] - mx); s += e[i]; }
    #pragma unroll
    for (int o = 16; o; o >>= 1) s += __shfl_xor_sync(0xffffffffu, s, o);
    float inv = 1.0f / s;

    float* dst = amap + ((size_t)b * QQ + q0 + w) * LL;
    #pragma unroll
    for (int i = 0; i < 32; i++) dst[lane + 32 * i] = e[i] * inv;
}

// ---------------------------------------------------------------------------
// Kernel 4 (HMMA bf16 split): unchanged from R6.
// ---------------------------------------------------------------------------
#define KC    32
#define NCH   (LL / KC)
#define ROWU  20
#define AHI_O 0
#define ALO_O (64 * ROWU)
#define BHI_O (2 * 64 * ROWU)
#define BLO_O (2 * 64 * ROWU + 128 * ROWU)
#define SM4U  (2 * 64 * ROWU + 2 * 128 * ROWU)

__global__ __launch_bounds__(256)
void k4_mma(const float* __restrict__ ctx,
            const float* __restrict__ amap,
            float* __restrict__ wc) {
    __shared__ __align__(16) uint32_t sm[SM4U];
    const uint32_t sb = smem_u32(sm);

    const int tid  = threadIdx.x;
    const int lane = tid & 31;
    const int wid  = tid >> 5;
    const int wm   = wid & 1;
    const int wn   = wid >> 1;

    const int b  = blockIdx.y;
    const int d0 = (blockIdx.x & 1) * 64;
    const int q0 = (blockIdx.x >> 1) * 128;

    const float* A  = ctx  + (size_t)b * DD * LL + (size_t)d0 * LL;
    const float* Bm = amap + ((size_t)b * QQ + q0) * LL;

    float acc[2][4][4];
    #pragma unroll
    for (int i = 0; i < 2; i++)
        #pragma unroll
        for (int j = 0; j < 4; j++)
            #pragma unroll
            for (int k = 0; k < 4; k++) acc[i][j][k] = 0.0f;

    const uint32_t a_row = wm * 32 + (lane & 15);
    const uint32_t a_col = (lane >> 4) * 16;
    const uint32_t b_rowbase = wn * 32 + ((lane >> 4) << 3) + (lane & 7);
    const uint32_t b_col = ((lane >> 3) & 1) * 16;

    for (int c = 0; c < NCH; c++) {
        const int l0 = c * KC;

        #pragma unroll
        for (int t = 0; t < 2; t++) {
            int idx = t * 256 + tid;
            int row = idx >> 3;
            int f   = idx & 7;
            float4 v = *(const float4*)(A + (size_t)row * LL + l0 + f * 4);
            uint32_t h0, l0p, h1, l1p;
            split2(v.x, v.y, h0, l0p);
            split2(v.z, v.w, h1, l1p);
            int o = row * ROWU + f * 2;
            sm[AHI_O + o] = h0; sm[AHI_O + o + 1] = h1;
            sm[ALO_O + o] = l0p; sm[ALO_O + o + 1] = l1p;
        }
        #pragma unroll
        for (int t = 0; t < 4; t++) {
            int idx = t * 256 + tid;
            int row = idx >> 3;
            int f   = idx & 7;
            float4 v = *(const float4*)(Bm + (size_t)row * LL + l0 + f * 4);
            uint32_t h0, l0p, h1, l1p;
            split2(v.x, v.y, h0, l0p);
            split2(v.z, v.w, h1, l1p);
            int o = row * ROWU + f * 2;
            sm[BHI_O + o] = h0; sm[BHI_O + o + 1] = h1;
            sm[BLO_O + o] = l0p; sm[BLO_O + o + 1] = l1p;
        }
        __syncthreads();

        #pragma unroll
        for (int ks = 0; ks < 2; ks++) {
            const uint32_t kbyte = ks * 32;

            uint32_t ah[2][4], al[2][4];
            #pragma unroll
            for (int mt = 0; mt < 2; mt++) {
                uint32_t addr = sb + 4 * (AHI_O + (a_row + mt * 16) * ROWU)
                              + kbyte + a_col;
                LDMATRIX_X4(ah[mt][0], ah[mt][1], ah[mt][2], ah[mt][3], addr);
                addr += 4 * (ALO_O - AHI_O);
                LDMATRIX_X4(al[mt][0], al[mt][1], al[mt][2], al[mt][3], addr);
            }
            uint32_t bh[4][2], bl[4][2];
            #pragma unroll
            for (int p = 0; p < 2; p++) {
                uint32_t addr = sb + 4 * (BHI_O + (b_rowbase + p * 16) * ROWU)
                              + kbyte + b_col;
                LDMATRIX_X4(bh[p * 2][0], bh[p * 2][1],
                            bh[p * 2 + 1][0], bh[p * 2 + 1][1], addr);
                addr += 4 * (BLO_O - BHI_O);
                LDMATRIX_X4(bl[p * 2][0], bl[p * 2][1],
                            bl[p * 2 + 1][0], bl[p * 2 + 1][1], addr);
            }

            #pragma unroll
            for (int mt = 0; mt < 2; mt++)
                #pragma unroll
                for (int nt = 0; nt < 4; nt++)
                    MMA_BF16(acc[mt][nt], ah[mt][0], ah[mt][1], ah[mt][2],
                             ah[mt][3], bh[nt][0], bh[nt][1]);
            #pragma unroll
            for (int mt = 0; mt < 2; mt++)
                #pragma unroll
                for (int nt = 0; nt < 4; nt++)
                    MMA_BF16(acc[mt][nt], ah[mt][0], ah[mt][1], ah[mt][2],
                             ah[mt][3], bl[nt][0], bl[nt][1]);
            #pragma unroll
            for (int mt = 0; mt < 2; mt++)
                #pragma unroll
                for (int nt = 0; nt < 4; nt++)
                    MMA_BF16(acc[mt][nt], al[mt][0], al[mt][1], al[mt][2],
                             al[mt][3], bh[nt][0], bh[nt][1]);
        }
        __syncthreads();
    }

    float* outb = wc + (size_t)b * DD * QQ;
    const int gid = lane >> 2;
    const int tig = lane & 3;
    #pragma unroll
    for (int mt = 0; mt < 2; mt++) {
        #pragma unroll
        for (int nt = 0; nt < 4; nt++) {
            int d = d0 + wm * 32 + mt * 16 + gid;
            int q = q0 + wn * 32 + nt * 8 + tig * 2;
            *(float2*)(outb + (size_t)d * QQ + q) =
                make_float2(acc[mt][nt][0], acc[mt][nt][1]);
            *(float2*)(outb + (size_t)(d + 8) * QQ + q) =
                make_float2(acc[mt][nt][2], acc[mt][nt][3]);
        }
    }
}

// ---------------------------------------------------------------------------
extern "C" void kernel_launch(void* const* d_in, const int* in_sizes, int n_in,
                              void* d_out, int out_size) {
    const float* query;
    const float* ctx;
    if ((size_t)in_sizes[0] == QUERY_ELEMS) {
        query = (const float*)d_in[0];
        ctx   = (const float*)d_in[1];
    } else {
        query = (const float*)d_in[1];
        ctx   = (const float*)d_in[0];
    }

    float* wc;
    float* amap;
    void* sym;
    if ((size_t)out_size >= WC_ELEMS + AMAP_ELEMS) {
        wc   = (float*)d_out;
        amap = (float*)d_out + WC_ELEMS;
    } else if ((size_t)out_size == WC_ELEMS) {
        wc = (float*)d_out;
        cudaGetSymbolAddress(&sym, g_scratch_amap);
        amap = (float*)sym;
    } else {
        cudaGetSymbolAddress(&sym, g_scratch_wc);
        wc = (float*)sym;
        amap = (float*)d_out;
    }

    const int SMEM_K3 = (32 * 1025) * sizeof(float);

    cudaFuncSetAttribute(k1_mma,
                         cudaFuncAttributeMaxDynamicSharedMemorySize, K1_SMEM_BYTES);
    cudaFuncSetAttribute(k3_softmax_l,
                         cudaFuncAttributeMaxDynamicSharedMemorySize, SMEM_K3);

    k1_mma<<<dim3(LL / 64, BB), 256, K1_SMEM_BYTES>>>(query, ctx);
    k3_softmax_l<<<dim3(QQ / 32, BB), 1024, SMEM_K3>>>(amap);
    k4_mma<<<dim3(4, BB), 256>>>(ctx, amap, wc);
}

// round 8
// speedup vs baseline: 1.0060x; 1.0060x over previous
#include <cuda_runtime.h>
#include <cuda_bf16.h>
#include <cstdint>
#include <math.h>

#define BB 128
#define DD 128
#define QQ 256
#define LL 1024
#define TEMP 4.0f

#define QUERY_ELEMS ((size_t)BB * DD * QQ)   // 4,194,304
#define WC_ELEMS    ((size_t)BB * DD * QQ)   // 4,194,304
#define AMAP_ELEMS  ((size_t)BB * QQ * LL)   // 33,554,432

__device__ __align__(16) float g_attn_q[(size_t)BB * LL * QQ];   // 134 MB
__device__ __align__(16) float g_scratch_amap[AMAP_ELEMS];       // fallback
__device__ __align__(16) float g_scratch_wc[WC_ELEMS];           // fallback

// ============================ helpers ======================================
__device__ __forceinline__ uint32_t smem_u32(const void* p) {
    uint32_t a;
    asm("{ .reg .u64 t; cvta.to.shared.u64 t, %1; cvt.u32.u64 %0, t; }"
        : "=r"(a) : "l"(p));
    return a;
}
__device__ __forceinline__ uint32_t pack2bf(float x, float y) {
    __nv_bfloat162 h = __floats2bfloat162_rn(x, y);
    return *(uint32_t*)&h;
}
__device__ __forceinline__ void split2(float x, float y,
                                       uint32_t& hi, uint32_t& lo) {
    __nv_bfloat16 hx = __float2bfloat16_rn(x);
    __nv_bfloat16 hy = __float2bfloat16_rn(y);
    float rx = x - __bfloat162float(hx);
    float ry = y - __bfloat162float(hy);
    __nv_bfloat162 h2; h2.x = hx; h2.y = hy;
    hi = *(uint32_t*)&h2;
    lo = pack2bf(rx, ry);
}
#define LDMATRIX_X4(r0, r1, r2, r3, addr) \
    asm volatile("ldmatrix.sync.aligned.m8n8.x4.shared.b16 {%0,%1,%2,%3}, [%4];" \
                 : "=r"(r0), "=r"(r1), "=r"(r2), "=r"(r3) : "r"(addr))
#define MMA_BF16(c, a0, a1, a2, a3, b0, b1) \
    asm volatile("mma.sync.aligned.m16n8k16.row.col.f32.bf16.bf16.f32 " \
                 "{%0,%1,%2,%3}, {%4,%5,%6,%7}, {%8,%9}, {%0,%1,%2,%3};" \
                 : "+f"((c)[0]), "+f"((c)[1]), "+f"((c)[2]), "+f"((c)[3]) \
                 : "r"(a0), "r"(a1), "r"(a2), "r"(a3), "r"(b0), "r"(b1))

// u32-index swizzle for K-major bf16-pair tiles (row = M/N index, col = u32 0..63)
__device__ __forceinline__ int swz(int row, int col) {
    return row * 64 + ((((col >> 2) ^ (row & 7)) << 2) | (col & 3));
}

// ---------------------------------------------------------------------------
// Kernel 1 (HMMA bf16 split, 512 threads): scores = ctx^T @ query, fused
// softmax over Q. CTA: M=64(l) x N=256(q), K=128(d) resident.
// 16 warps = 2(m) x 8(n); warp tile 32x32; acc 32 regs/thread.
// grid (16, B). smem 160 KB, reused as scores[64][264] for the epilogue.
// ---------------------------------------------------------------------------
#define K1_AHI 0
#define K1_ALO 4096
#define K1_BHI 8192
#define K1_BLO 24576
#define K1_SMEM_BYTES (40960 * 4)   // 160 KB

__global__ __launch_bounds__(512, 1)
void k1_mma(const float* __restrict__ query,
            const float* __restrict__ ctx) {
    extern __shared__ __align__(16) uint32_t sm1u[];
    const uint32_t sb = smem_u32(sm1u);

    const int tid  = threadIdx.x;
    const int lane = tid & 31;
    const int wid  = tid >> 5;       // 0..15
    const int wm   = wid & 1;        // 0..1 : 32 l-rows each
    const int wn   = wid >> 1;       // 0..7 : 32 q-cols each

    const int b  = blockIdx.y;
    const int l0 = blockIdx.x * 64;

    const float* ctxb = ctx + (size_t)b * DD * LL;
    const float* qb   = query + (size_t)b * DD * QQ;

    // ---- fill A: 64 l x 128 d (transpose + split). 1024 units, 2/thread ----
    #pragma unroll
    for (int t = 0; t < 2; t++) {
        int u  = t * 512 + tid;
        int lu = u & 15;             // l-group (4 l each)
        int du = u >> 4;             // d-pair 0..63
        int l  = lu * 4;
        int d  = du * 2;
        float4 v0 = *(const float4*)(ctxb + (size_t)d * LL + l0 + l);
        float4 v1 = *(const float4*)(ctxb + (size_t)(d + 1) * LL + l0 + l);
        const float a0[4] = {v0.x, v0.y, v0.z, v0.w};
        const float a1[4] = {v1.x, v1.y, v1.z, v1.w};
        #pragma unroll
        for (int j = 0; j < 4; j++) {
            uint32_t hi, lo;
            split2(a0[j], a1[j], hi, lo);
            int o = swz(l + j, du);
            sm1u[K1_AHI + o] = hi;
            sm1u[K1_ALO + o] = lo;
        }
    }
    // ---- fill B: 256 q x 128 d (transpose + split). 4096 units, 8/thread ----
    #pragma unroll
    for (int t = 0; t < 8; t++) {
        int u  = t * 512 + tid;
        int qu = u & 63;             // q-group (4 q each)
        int du = u >> 6;             // d-pair 0..63
        int q  = qu * 4;
        int d  = du * 2;
        float4 v0 = *(const float4*)(qb + (size_t)d * QQ + q);
        float4 v1 = *(const float4*)(qb + (size_t)(d + 1) * QQ + q);
        const float b0[4] = {v0.x, v0.y, v0.z, v0.w};
        const float b1[4] = {v1.x, v1.y, v1.z, v1.w};
        #pragma unroll
        for (int j = 0; j < 4; j++) {
            uint32_t hi, lo;
            split2(b0[j], b1[j], hi, lo);
            int o = swz(q + j, du);
            sm1u[K1_BHI + o] = hi;
            sm1u[K1_BLO + o] = lo;
        }
    }
    __syncthreads();

    float acc[2][4][4];
    #pragma unroll
    for (int i = 0; i < 2; i++)
        #pragma unroll
        for (int j = 0; j < 4; j++)
            #pragma unroll
            for (int k = 0; k < 4; k++) acc[i][j][k] = 0.0f;

    // ---- MMA: 8 k16 steps x 3 split passes ----
    for (int ks = 0; ks < 8; ks++) {
        uint32_t ah[2][4], al[2][4];
        #pragma unroll
        for (int mt = 0; mt < 2; mt++) {
            int row = wm * 32 + mt * 16 + (lane & 15);
            int ch  = 2 * ks + (lane >> 4);
            uint32_t off = (uint32_t)(row * 256 + ((ch ^ (row & 7)) << 4));
            LDMATRIX_X4(ah[mt][0], ah[mt][1], ah[mt][2], ah[mt][3],
                        sb + K1_AHI * 4 + off);
            LDMATRIX_X4(al[mt][0], al[mt][1], al[mt][2], al[mt][3],
                        sb + K1_ALO * 4 + off);
        }
        #pragma unroll
        for (int p = 0; p < 2; p++) {            // 2 n8-tiles per x4
            int row = wn * 32 + p * 16 + ((lane >> 4) << 3) + (lane & 7);
            int ch  = 2 * ks + ((lane >> 3) & 1);
            uint32_t off = (uint32_t)(row * 256 + ((ch ^ (row & 7)) << 4));
            uint32_t bh0, bh1, bh2, bh3, bl0, bl1, bl2, bl3;
            LDMATRIX_X4(bh0, bh1, bh2, bh3, sb + K1_BHI * 4 + off);
            LDMATRIX_X4(bl0, bl1, bl2, bl3, sb + K1_BLO * 4 + off);
            #pragma unroll
            for (int mt = 0; mt < 2; mt++) {
                MMA_BF16(acc[mt][p * 2],     ah[mt][0], ah[mt][1], ah[mt][2], ah[mt][3], bh0, bh1);
                MMA_BF16(acc[mt][p * 2 + 1], ah[mt][0], ah[mt][1], ah[mt][2], ah[mt][3], bh2, bh3);
                MMA_BF16(acc[mt][p * 2],     ah[mt][0], ah[mt][1], ah[mt][2], ah[mt][3], bl0, bl1);
                MMA_BF16(acc[mt][p * 2 + 1], ah[mt][0], ah[mt][1], ah[mt][2], ah[mt][3], bl2, bl3);
                MMA_BF16(acc[mt][p * 2],     al[mt][0], al[mt][1], al[mt][2], al[mt][3], bh0, bh1);
                MMA_BF16(acc[mt][p * 2 + 1], al[mt][0], al[mt][1], al[mt][2], al[mt][3], bh2, bh3);
            }
        }
    }
    __syncthreads();   // smem A/B dead; reuse as scores

    // ---- scores to smem: 64 rows x 264 fp32 ----
    float* sc = (float*)sm1u;
    const int gid = lane >> 2;
    const int tig = lane & 3;
    #pragma unroll
    for (int mt = 0; mt < 2; mt++) {
        int r0 = wm * 32 + mt * 16 + gid;
        #pragma unroll
        for (int nt = 0; nt < 4; nt++) {
            int q = wn * 32 + nt * 8 + tig * 2;
            *(float2*)(sc + (size_t)r0 * 264 + q) =
                make_float2(acc[mt][nt][0], acc[mt][nt][1]);
            *(float2*)(sc + (size_t)(r0 + 8) * 264 + q) =
                make_float2(acc[mt][nt][2], acc[mt][nt][3]);
        }
    }
    __syncthreads();

    // ---- fused softmax over Q: warp wid owns rows wid*4..+3 ----
    const size_t outb = ((size_t)b * LL + l0 + wid * 4) * QQ;
    #pragma unroll
    for (int i = 0; i < 4; i++) {
        const float* row = sc + (size_t)(wid * 4 + i) * 264;
        float e[8];
        float m = -1e30f;
        #pragma unroll
        for (int j = 0; j < 8; j++) { e[j] = row[lane + j * 32]; m = fmaxf(m, e[j]); }
        #pragma unroll
        for (int o = 16; o; o >>= 1) m = fmaxf(m, __shfl_xor_sync(0xffffffffu, m, o));
        float s = 0.0f;
        #pragma unroll
        for (int j = 0; j < 8; j++) { e[j] = __expf(e[j] - m); s += e[j]; }
        #pragma unroll
        for (int o = 16; o; o >>= 1) s += __shfl_xor_sync(0xffffffffu, s, o);
        float inv = 1.0f / s;
        #pragma unroll
        for (int j = 0; j < 8; j++)
            g_attn_q[outb + (size_t)i * QQ + lane + j * 32] = e[j] * inv;
    }
}

// ---------------------------------------------------------------------------
// Kernel 3: attn_c[b,q,l] = softmax_l(TEMP * attn_q[b,l,q]). (unchanged)
// ---------------------------------------------------------------------------
__global__ void k3_softmax_l(float* __restrict__ amap) {
    extern __shared__ float sm3[];

    const int tid  = threadIdx.x;
    const int b    = blockIdx.y;
    const int q0   = blockIdx.x * 32;
    const int w    = tid >> 5;
    const int lane = tid & 31;

    const float* src = g_attn_q + (size_t)b * LL * QQ + q0;
    #pragma unroll
    for (int i = 0; i < 32; i++) {
        int l = i * 32 + w;
        sm3[lane * 1025 + l] = src[(size_t)l * QQ + lane];
    }
    __syncthreads();

    const float* row = sm3 + w * 1025;
    float e[32];
    float mx = -1e30f;
    #pragma unroll
    for (int i = 0; i < 32; i++) {
        float v = TEMP * row[lane + 32 * i];
        e[i] = v;
        mx = fmaxf(mx, v);
    }
    #pragma unroll
    for (int o = 16; o; o >>= 1) mx = fmaxf(mx, __shfl_xor_sync(0xffffffffu, mx, o));

    float s = 0.0f;
    #pragma unroll
    for (int i = 0; i < 32; i++) { e[i] = __expf(e[i] - mx); s += e[i]; }
    #pragma unroll
    for (int o = 16; o; o >>= 1) s += __shfl_xor_sync(0xffffffffu, s, o);
    float inv = 1.0f / s;

    float* dst = amap + ((size_t)b * QQ + q0 + w) * LL;
    #pragma unroll
    for (int i = 0; i < 32; i++) dst[lane + 32 * i] = e[i] * inv;
}

// ---------------------------------------------------------------------------
// Kernel 4 (HMMA bf16 split): unchanged from R6.
// ---------------------------------------------------------------------------
#define KC    32
#define NCH   (LL / KC)
#define ROWU  20
#define AHI_O 0
#define ALO_O (64 * ROWU)
#define BHI_O (2 * 64 * ROWU)
#define BLO_O (2 * 64 * ROWU + 128 * ROWU)
#define SM4U  (2 * 64 * ROWU + 2 * 128 * ROWU)

__global__ __launch_bounds__(256)
void k4_mma(const float* __restrict__ ctx,
            const float* __restrict__ amap,
            float* __restrict__ wc) {
    __shared__ __align__(16) uint32_t sm[SM4U];
    const uint32_t sb = smem_u32(sm);

    const int tid  = threadIdx.x;
    const int lane = tid & 31;
    const int wid  = tid >> 5;
    const int wm   = wid & 1;
    const int wn   = wid >> 1;

    const int b  = blockIdx.y;
    const int d0 = (blockIdx.x & 1) * 64;
    const int q0 = (blockIdx.x >> 1) * 128;

    const float* A  = ctx  + (size_t)b * DD * LL + (size_t)d0 * LL;
    const float* Bm = amap + ((size_t)b * QQ + q0) * LL;

    float acc[2][4][4];
    #pragma unroll
    for (int i = 0; i < 2; i++)
        #pragma unroll
        for (int j = 0; j < 4; j++)
            #pragma unroll
            for (int k = 0; k < 4; k++) acc[i][j][k] = 0.0f;

    const uint32_t a_row = wm * 32 + (lane & 15);
    const uint32_t a_col = (lane >> 4) * 16;
    const uint32_t b_rowbase = wn * 32 + ((lane >> 4) << 3) + (lane & 7);
    const uint32_t b_col = ((lane >> 3) & 1) * 16;

    for (int c = 0; c < NCH; c++) {
        const int l0 = c * KC;

        #pragma unroll
        for (int t = 0; t < 2; t++) {
            int idx = t * 256 + tid;
            int row = idx >> 3;
            int f   = idx & 7;
            float4 v = *(const float4*)(A + (size_t)row * LL + l0 + f * 4);
            uint32_t h0, l0p, h1, l1p;
            split2(v.x, v.y, h0, l0p);
            split2(v.z, v.w, h1, l1p);
            int o = row * ROWU + f * 2;
            sm[AHI_O + o] = h0; sm[AHI_O + o + 1] = h1;
            sm[ALO_O + o] = l0p; sm[ALO_O + o + 1] = l1p;
        }
        #pragma unroll
        for (int t = 0; t < 4; t++) {
            int idx = t * 256 + tid;
            int row = idx >> 3;
            int f   = idx & 7;
            float4 v = *(const float4*)(Bm + (size_t)row * LL + l0 + f * 4);
            uint32_t h0, l0p, h1, l1p;
            split2(v.x, v.y, h0, l0p);
            split2(v.z, v.w, h1, l1p);
            int o = row * ROWU + f * 2;
            sm[BHI_O + o] = h0; sm[BHI_O + o + 1] = h1;
            sm[BLO_O + o] = l0p; sm[BLO_O + o + 1] = l1p;
        }
        __syncthreads();

        #pragma unroll
        for (int ks = 0; ks < 2; ks++) {
            const uint32_t kbyte = ks * 32;

            uint32_t ah[2][4], al[2][4];
            #pragma unroll
            for (int mt = 0; mt < 2; mt++) {
                uint32_t addr = sb + 4 * (AHI_O + (a_row + mt * 16) * ROWU)
                              + kbyte + a_col;
                LDMATRIX_X4(ah[mt][0], ah[mt][1], ah[mt][2], ah[mt][3], addr);
                addr += 4 * (ALO_O - AHI_O);
                LDMATRIX_X4(al[mt][0], al[mt][1], al[mt][2], al[mt][3], addr);
            }
            uint32_t bh[4][2], bl[4][2];
            #pragma unroll
            for (int p = 0; p < 2; p++) {
                uint32_t addr = sb + 4 * (BHI_O + (b_rowbase + p * 16) * ROWU)
                              + kbyte + b_col;
                LDMATRIX_X4(bh[p * 2][0], bh[p * 2][1],
                            bh[p * 2 + 1][0], bh[p * 2 + 1][1], addr);
                addr += 4 * (BLO_O - BHI_O);
                LDMATRIX_X4(bl[p * 2][0], bl[p * 2][1],
                            bl[p * 2 + 1][0], bl[p * 2 + 1][1], addr);
            }

            #pragma unroll
            for (int mt = 0; mt < 2; mt++)
                #pragma unroll
                for (int nt = 0; nt < 4; nt++)
                    MMA_BF16(acc[mt][nt], ah[mt][0], ah[mt][1], ah[mt][2],
                             ah[mt][3], bh[nt][0], bh[nt][1]);
            #pragma unroll
            for (int mt = 0; mt < 2; mt++)
                #pragma unroll
                for (int nt = 0; nt < 4; nt++)
                    MMA_BF16(acc[mt][nt], ah[mt][0], ah[mt][1], ah[mt][2],
                             ah[mt][3], bl[nt][0], bl[nt][1]);
            #pragma unroll
            for (int mt = 0; mt < 2; mt++)
                #pragma unroll
                for (int nt = 0; nt < 4; nt++)
                    MMA_BF16(acc[mt][nt], al[mt][0], al[mt][1], al[mt][2],
                             al[mt][3], bh[nt][0], bh[nt][1]);
        }
        __syncthreads();
    }

    float* outb = wc + (size_t)b * DD * QQ;
    const int gid = lane >> 2;
    const int tig = lane & 3;
    #pragma unroll
    for (int mt = 0; mt < 2; mt++) {
        #pragma unroll
        for (int nt = 0; nt < 4; nt++) {
            int d = d0 + wm * 32 + mt * 16 + gid;
            int q = q0 + wn * 32 + nt * 8 + tig * 2;
            *(float2*)(outb + (size_t)d * QQ + q) =
                make_float2(acc[mt][nt][0], acc[mt][nt][1]);
            *(float2*)(outb + (size_t)(d + 8) * QQ + q) =
                make_float2(acc[mt][nt][2], acc[mt][nt][3]);
        }
    }
}

// ---------------------------------------------------------------------------
extern "C" void kernel_launch(void* const* d_in, const int* in_sizes, int n_in,
                              void* d_out, int out_size) {
    const float* query;
    const float* ctx;
    if ((size_t)in_sizes[0] == QUERY_ELEMS) {
        query = (const float*)d_in[0];
        ctx   = (const float*)d_in[1];
    } else {
        query = (const float*)d_in[1];
        ctx   = (const float*)d_in[0];
    }

    float* wc;
    float* amap;
    void* sym;
    if ((size_t)out_size >= WC_ELEMS + AMAP_ELEMS) {
        wc   = (float*)d_out;
        amap = (float*)d_out + WC_ELEMS;
    } else if ((size_t)out_size == WC_ELEMS) {
        wc = (float*)d_out;
        cudaGetSymbolAddress(&sym, g_scratch_amap);
        amap = (float*)sym;
    } else {
        cudaGetSymbolAddress(&sym, g_scratch_wc);
        wc = (float*)sym;
        amap = (float*)d_out;
    }

    const int SMEM_K3 = (32 * 1025) * sizeof(float);

    cudaFuncSetAttribute(k1_mma,
                         cudaFuncAttributeMaxDynamicSharedMemorySize, K1_SMEM_BYTES);
    cudaFuncSetAttribute(k3_softmax_l,
                         cudaFuncAttributeMaxDynamicSharedMemorySize, SMEM_K3);

    k1_mma<<<dim3(LL / 64, BB), 512, K1_SMEM_BYTES>>>(query, ctx);
    k3_softmax_l<<<dim3(QQ / 32, BB), 1024, SMEM_K3>>>(amap);
    k4_mma<<<dim3(4, BB), 256>>>(ctx, amap, wc);
}

// round 9
// speedup vs baseline: 1.0104x; 1.0044x over previous
#include <cuda_runtime.h>
#include <cuda_bf16.h>
#include <cstdint>
#include <math.h>

#define BB 128
#define DD 128
#define QQ 256
#define LL 1024
#define TEMP 4.0f

#define QUERY_ELEMS ((size_t)BB * DD * QQ)   // 4,194,304
#define WC_ELEMS    ((size_t)BB * DD * QQ)   // 4,194,304
#define AMAP_ELEMS  ((size_t)BB * QQ * LL)   // 33,554,432

__device__ __align__(16) float g_attn_q[(size_t)BB * LL * QQ];   // 134 MB
__device__ __align__(16) float g_scratch_amap[AMAP_ELEMS];       // fallback
__device__ __align__(16) float g_scratch_wc[WC_ELEMS];           // fallback

// ============================ helpers ======================================
__device__ __forceinline__ uint32_t smem_u32(const void* p) {
    uint32_t a;
    asm("{ .reg .u64 t; cvta.to.shared.u64 t, %1; cvt.u32.u64 %0, t; }"
        : "=r"(a) : "l"(p));
    return a;
}
__device__ __forceinline__ uint32_t pack2bf(float x, float y) {
    __nv_bfloat162 h = __floats2bfloat162_rn(x, y);
    return *(uint32_t*)&h;
}
__device__ __forceinline__ void split2(float x, float y,
                                       uint32_t& hi, uint32_t& lo) {
    __nv_bfloat16 hx = __float2bfloat16_rn(x);
    __nv_bfloat16 hy = __float2bfloat16_rn(y);
    float rx = x - __bfloat162float(hx);
    float ry = y - __bfloat162float(hy);
    __nv_bfloat162 h2; h2.x = hx; h2.y = hy;
    hi = *(uint32_t*)&h2;
    lo = pack2bf(rx, ry);
}
#define LDMATRIX_X4(r0, r1, r2, r3, addr) \
    asm volatile("ldmatrix.sync.aligned.m8n8.x4.shared.b16 {%0,%1,%2,%3}, [%4];" \
                 : "=r"(r0), "=r"(r1), "=r"(r2), "=r"(r3) : "r"(addr))
#define MMA_BF16(c, a0, a1, a2, a3, b0, b1) \
    asm volatile("mma.sync.aligned.m16n8k16.row.col.f32.bf16.bf16.f32 " \
                 "{%0,%1,%2,%3}, {%4,%5,%6,%7}, {%8,%9}, {%0,%1,%2,%3};" \
                 : "+f"((c)[0]), "+f"((c)[1]), "+f"((c)[2]), "+f"((c)[3]) \
                 : "r"(a0), "r"(a1), "r"(a2), "r"(a3), "r"(b0), "r"(b1))

// u32-index swizzle for K-major bf16-pair tiles (row = M/N index, col = u32 0..63)
__device__ __forceinline__ int swz(int row, int col) {
    return row * 64 + ((((col >> 2) ^ (row & 7)) << 2) | (col & 3));
}

// ---------------------------------------------------------------------------
// Kernel 1 (HMMA bf16 split, 512 threads): scores = ctx^T @ query, fused
// softmax over Q. CTA: M=64(l) x N=256(q), K=128(d) resident.
// 16 warps = 2(m) x 8(n); warp tile 32x32; acc 32 regs/thread.
// grid (16, B). smem 160 KB, reused as scores[64][264] for the epilogue.
// ---------------------------------------------------------------------------
#define K1_AHI 0
#define K1_ALO 4096
#define K1_BHI 8192
#define K1_BLO 24576
#define K1_SMEM_BYTES (40960 * 4)   // 160 KB

__global__ __launch_bounds__(512, 1)
void k1_mma(const float* __restrict__ query,
            const float* __restrict__ ctx) {
    extern __shared__ __align__(16) uint32_t sm1u[];
    const uint32_t sb = smem_u32(sm1u);

    const int tid  = threadIdx.x;
    const int lane = tid & 31;
    const int wid  = tid >> 5;       // 0..15
    const int wm   = wid & 1;        // 0..1 : 32 l-rows each
    const int wn   = wid >> 1;       // 0..7 : 32 q-cols each

    const int b  = blockIdx.y;
    const int l0 = blockIdx.x * 64;

    const float* ctxb = ctx + (size_t)b * DD * LL;
    const float* qb   = query + (size_t)b * DD * QQ;

    // ---- fill A: 64 l x 128 d (transpose + split). 1024 units, 2/thread ----
    #pragma unroll
    for (int t = 0; t < 2; t++) {
        int u  = t * 512 + tid;
        int lu = u & 15;             // l-group (4 l each)
        int du = u >> 4;             // d-pair 0..63
        int l  = lu * 4;
        int d  = du * 2;
        float4 v0 = *(const float4*)(ctxb + (size_t)d * LL + l0 + l);
        float4 v1 = *(const float4*)(ctxb + (size_t)(d + 1) * LL + l0 + l);
        const float a0[4] = {v0.x, v0.y, v0.z, v0.w};
        const float a1[4] = {v1.x, v1.y, v1.z, v1.w};
        #pragma unroll
        for (int j = 0; j < 4; j++) {
            uint32_t hi, lo;
            split2(a0[j], a1[j], hi, lo);
            int o = swz(l + j, du);
            sm1u[K1_AHI + o] = hi;
            sm1u[K1_ALO + o] = lo;
        }
    }
    // ---- fill B: 256 q x 128 d (transpose + split). 4096 units, 8/thread ----
    #pragma unroll
    for (int t = 0; t < 8; t++) {
        int u  = t * 512 + tid;
        int qu = u & 63;             // q-group (4 q each)
        int du = u >> 6;             // d-pair 0..63
        int q  = qu * 4;
        int d  = du * 2;
        float4 v0 = *(const float4*)(qb + (size_t)d * QQ + q);
        float4 v1 = *(const float4*)(qb + (size_t)(d + 1) * QQ + q);
        const float b0[4] = {v0.x, v0.y, v0.z, v0.w};
        const float b1[4] = {v1.x, v1.y, v1.z, v1.w};
        #pragma unroll
        for (int j = 0; j < 4; j++) {
            uint32_t hi, lo;
            split2(b0[j], b1[j], hi, lo);
            int o = swz(q + j, du);
            sm1u[K1_BHI + o] = hi;
            sm1u[K1_BLO + o] = lo;
        }
    }
    __syncthreads();

    float acc[2][4][4];
    #pragma unroll
    for (int i = 0; i < 2; i++)
        #pragma unroll
        for (int j = 0; j < 4; j++)
            #pragma unroll
            for (int k = 0; k < 4; k++) acc[i][j][k] = 0.0f;

    // ---- MMA: 8 k16 steps x 3 split passes ----
    for (int ks = 0; ks < 8; ks++) {
        uint32_t ah[2][4], al[2][4];
        #pragma unroll
        for (int mt = 0; mt < 2; mt++) {
            int row = wm * 32 + mt * 16 + (lane & 15);
            int ch  = 2 * ks + (lane >> 4);
            uint32_t off = (uint32_t)(row * 256 + ((ch ^ (row & 7)) << 4));
            LDMATRIX_X4(ah[mt][0], ah[mt][1], ah[mt][2], ah[mt][3],
                        sb + K1_AHI * 4 + off);
            LDMATRIX_X4(al[mt][0], al[mt][1], al[mt][2], al[mt][3],
                        sb + K1_ALO * 4 + off);
        }
        #pragma unroll
        for (int p = 0; p < 2; p++) {            // 2 n8-tiles per x4
            int row = wn * 32 + p * 16 + ((lane >> 4) << 3) + (lane & 7);
            int ch  = 2 * ks + ((lane >> 3) & 1);
            uint32_t off = (uint32_t)(row * 256 + ((ch ^ (row & 7)) << 4));
            uint32_t bh0, bh1, bh2, bh3, bl0, bl1, bl2, bl3;
            LDMATRIX_X4(bh0, bh1, bh2, bh3, sb + K1_BHI * 4 + off);
            LDMATRIX_X4(bl0, bl1, bl2, bl3, sb + K1_BLO * 4 + off);
            #pragma unroll
            for (int mt = 0; mt < 2; mt++) {
                MMA_BF16(acc[mt][p * 2],     ah[mt][0], ah[mt][1], ah[mt][2], ah[mt][3], bh0, bh1);
                MMA_BF16(acc[mt][p * 2 + 1], ah[mt][0], ah[mt][1], ah[mt][2], ah[mt][3], bh2, bh3);
                MMA_BF16(acc[mt][p * 2],     ah[mt][0], ah[mt][1], ah[mt][2], ah[mt][3], bl0, bl1);
                MMA_BF16(acc[mt][p * 2 + 1], ah[mt][0], ah[mt][1], ah[mt][2], ah[mt][3], bl2, bl3);
                MMA_BF16(acc[mt][p * 2],     al[mt][0], al[mt][1], al[mt][2], al[mt][3], bh0, bh1);
                MMA_BF16(acc[mt][p * 2 + 1], al[mt][0], al[mt][1], al[mt][2], al[mt][3], bh2, bh3);
            }
        }
    }
    __syncthreads();   // smem A/B dead; reuse as scores

    // ---- scores to smem: 64 rows x 264 fp32 ----
    float* sc = (float*)sm1u;
    const int gid = lane >> 2;
    const int tig = lane & 3;
    #pragma unroll
    for (int mt = 0; mt < 2; mt++) {
        int r0 = wm * 32 + mt * 16 + gid;
        #pragma unroll
        for (int nt = 0; nt < 4; nt++) {
            int q = wn * 32 + nt * 8 + tig * 2;
            *(float2*)(sc + (size_t)r0 * 264 + q) =
                make_float2(acc[mt][nt][0], acc[mt][nt][1]);
            *(float2*)(sc + (size_t)(r0 + 8) * 264 + q) =
                make_float2(acc[mt][nt][2], acc[mt][nt][3]);
        }
    }
    __syncthreads();

    // ---- fused softmax over Q: warp wid owns rows wid*4..+3 ----
    const size_t outb = ((size_t)b * LL + l0 + wid * 4) * QQ;
    #pragma unroll
    for (int i = 0; i < 4; i++) {
        const float* row = sc + (size_t)(wid * 4 + i) * 264;
        float e[8];
        float m = -1e30f;
        #pragma unroll
        for (int j = 0; j < 8; j++) { e[j] = row[lane + j * 32]; m = fmaxf(m, e[j]); }
        #pragma unroll
        for (int o = 16; o; o >>= 1) m = fmaxf(m, __shfl_xor_sync(0xffffffffu, m, o));
        float s = 0.0f;
        #pragma unroll
        for (int j = 0; j < 8; j++) { e[j] = __expf(e[j] - m); s += e[j]; }
        #pragma unroll
        for (int o = 16; o; o >>= 1) s += __shfl_xor_sync(0xffffffffu, s, o);
        float inv = 1.0f / s;
        #pragma unroll
        for (int j = 0; j < 8; j++)
            g_attn_q[outb + (size_t)i * QQ + lane + j * 32] = e[j] * inv;
    }
}

// ---------------------------------------------------------------------------
// Kernel 3: attn_c[b,q,l] = softmax_l(TEMP * attn_q[b,l,q]). (unchanged)
// ---------------------------------------------------------------------------
__global__ void k3_softmax_l(float* __restrict__ amap) {
    extern __shared__ float sm3[];

    const int tid  = threadIdx.x;
    const int b    = blockIdx.y;
    const int q0   = blockIdx.x * 32;
    const int w    = tid >> 5;
    const int lane = tid & 31;

    const float* src = g_attn_q + (size_t)b * LL * QQ + q0;
    #pragma unroll
    for (int i = 0; i < 32; i++) {
        int l = i * 32 + w;
        sm3[lane * 1025 + l] = src[(size_t)l * QQ + lane];
    }
    __syncthreads();

    const float* row = sm3 + w * 1025;
    float e[32];
    float mx = -1e30f;
    #pragma unroll
    for (int i = 0; i < 32; i++) {
        float v = TEMP * row[lane + 32 * i];
        e[i] = v;
        mx = fmaxf(mx, v);
    }
    #pragma unroll
    for (int o = 16; o; o >>= 1) mx = fmaxf(mx, __shfl_xor_sync(0xffffffffu, mx, o));

    float s = 0.0f;
    #pragma unroll
    for (int i = 0; i < 32; i++) { e[i] = __expf(e[i] - mx); s += e[i]; }
    #pragma unroll
    for (int o = 16; o; o >>= 1) s += __shfl_xor_sync(0xffffffffu, s, o);
    float inv = 1.0f / s;

    float* dst = amap + ((size_t)b * QQ + q0 + w) * LL;
    #pragma unroll
    for (int i = 0; i < 32; i++) dst[lane + 32 * i] = e[i] * inv;
}

// ---------------------------------------------------------------------------
// Kernel 4 (HMMA bf16 split): unchanged from R6.
// ---------------------------------------------------------------------------
#define KC    32
#define NCH   (LL / KC)
#define ROWU  20
#define AHI_O 0
#define ALO_O (64 * ROWU)
#define BHI_O (2 * 64 * ROWU)
#define BLO_O (2 * 64 * ROWU + 128 * ROWU)
#define SM4U  (2 * 64 * ROWU + 2 * 128 * ROWU)

__global__ __launch_bounds__(256)
void k4_mma(const float* __restrict__ ctx,
            const float* __restrict__ amap,
            float* __restrict__ wc) {
    __shared__ __align__(16) uint32_t sm[SM4U];
    const uint32_t sb = smem_u32(sm);

    const int tid  = threadIdx.x;
    const int lane = tid & 31;
    const int wid  = tid >> 5;
    const int wm   = wid & 1;
    const int wn   = wid >> 1;

    const int b  = blockIdx.y;
    const int d0 = (blockIdx.x & 1) * 64;
    const int q0 = (blockIdx.x >> 1) * 128;

    const float* A  = ctx  + (size_t)b * DD * LL + (size_t)d0 * LL;
    const float* Bm = amap + ((size_t)b * QQ + q0) * LL;

    float acc[2][4][4];
    #pragma unroll
    for (int i = 0; i < 2; i++)
        #pragma unroll
        for (int j = 0; j < 4; j++)
            #pragma unroll
            for (int k = 0; k < 4; k++) acc[i][j][k] = 0.0f;

    const uint32_t a_row = wm * 32 + (lane & 15);
    const uint32_t a_col = (lane >> 4) * 16;
    const uint32_t b_rowbase = wn * 32 + ((lane >> 4) << 3) + (lane & 7);
    const uint32_t b_col = ((lane >> 3) & 1) * 16;

    for (int c = 0; c < NCH; c++) {
        const int l0 = c * KC;

        #pragma unroll
        for (int t = 0; t < 2; t++) {
            int idx = t * 256 + tid;
            int row = idx >> 3;
            int f   = idx & 7;
            float4 v = *(const float4*)(A + (size_t)row * LL + l0 + f * 4);
            uint32_t h0, l0p, h1, l1p;
            split2(v.x, v.y, h0, l0p);
            split2(v.z, v.w, h1, l1p);
            int o = row * ROWU + f * 2;
            sm[AHI_O + o] = h0; sm[AHI_O + o + 1] = h1;
            sm[ALO_O + o] = l0p; sm[ALO_O + o + 1] = l1p;
        }
        #pragma unroll
        for (int t = 0; t < 4; t++) {
            int idx = t * 256 + tid;
            int row = idx >> 3;
            int f   = idx & 7;
            float4 v = *(const float4*)(Bm + (size_t)row * LL + l0 + f * 4);
            uint32_t h0, l0p, h1, l1p;
            split2(v.x, v.y, h0, l0p);
            split2(v.z, v.w, h1, l1p);
            int o = row * ROWU + f * 2;
            sm[BHI_O + o] = h0; sm[BHI_O + o + 1] = h1;
            sm[BLO_O + o] = l0p; sm[BLO_O + o + 1] = l1p;
        }
        __syncthreads();

        #pragma unroll
        for (int ks = 0; ks < 2; ks++) {
            const uint32_t kbyte = ks * 32;

            uint32_t ah[2][4], al[2][4];
            #pragma unroll
            for (int mt = 0; mt < 2; mt++) {
                uint32_t addr = sb + 4 * (AHI_O + (a_row + mt * 16) * ROWU)
                              + kbyte + a_col;
                LDMATRIX_X4(ah[mt][0], ah[mt][1], ah[mt][2], ah[mt][3], addr);
                addr += 4 * (ALO_O - AHI_O);
                LDMATRIX_X4(al[mt][0], al[mt][1], al[mt][2], al[mt][3], addr);
            }
            uint32_t bh[4][2], bl[4][2];
            #pragma unroll
            for (int p = 0; p < 2; p++) {
                uint32_t addr = sb + 4 * (BHI_O + (b_rowbase + p * 16) * ROWU)
                              + kbyte + b_col;
                LDMATRIX_X4(bh[p * 2][0], bh[p * 2][1],
                            bh[p * 2 + 1][0], bh[p * 2 + 1][1], addr);
                addr += 4 * (BLO_O - BHI_O);
                LDMATRIX_X4(bl[p * 2][0], bl[p * 2][1],
                            bl[p * 2 + 1][0], bl[p * 2 + 1][1], addr);
            }

            #pragma unroll
            for (int mt = 0; mt < 2; mt++)
                #pragma unroll
                for (int nt = 0; nt < 4; nt++)
                    MMA_BF16(acc[mt][nt], ah[mt][0], ah[mt][1], ah[mt][2],
                             ah[mt][3], bh[nt][0], bh[nt][1]);
            #pragma unroll
            for (int mt = 0; mt < 2; mt++)
                #pragma unroll
                for (int nt = 0; nt < 4; nt++)
                    MMA_BF16(acc[mt][nt], ah[mt][0], ah[mt][1], ah[mt][2],
                             ah[mt][3], bl[nt][0], bl[nt][1]);
            #pragma unroll
            for (int mt = 0; mt < 2; mt++)
                #pragma unroll
                for (int nt = 0; nt < 4; nt++)
                    MMA_BF16(acc[mt][nt], al[mt][0], al[mt][1], al[mt][2],
                             al[mt][3], bh[nt][0], bh[nt][1]);
        }
        __syncthreads();
    }

    float* outb = wc + (size_t)b * DD * QQ;
    const int gid = lane >> 2;
    const int tig = lane & 3;
    #pragma unroll
    for (int mt = 0; mt < 2; mt++) {
        #pragma unroll
        for (int nt = 0; nt < 4; nt++) {
            int d = d0 + wm * 32 + mt * 16 + gid;
            int q = q0 + wn * 32 + nt * 8 + tig * 2;
            *(float2*)(outb + (size_t)d * QQ + q) =
                make_float2(acc[mt][nt][0], acc[mt][nt][1]);
            *(float2*)(outb + (size_t)(d + 8) * QQ + q) =
                make_float2(acc[mt][nt][2], acc[mt][nt][3]);
        }
    }
}

// ---------------------------------------------------------------------------
extern "C" void kernel_launch(void* const* d_in, const int* in_sizes, int n_in,
                              void* d_out, int out_size) {
    const float* query;
    const float* ctx;
    if ((size_t)in_sizes[0] == QUERY_ELEMS) {
        query = (const float*)d_in[0];
        ctx   = (const float*)d_in[1];
    } else {
        query = (const float*)d_in[1];
        ctx   = (const float*)d_in[0];
    }

    float* wc;
    float* amap;
    void* sym;
    if ((size_t)out_size >= WC_ELEMS + AMAP_ELEMS) {
        wc   = (float*)d_out;
        amap = (float*)d_out + WC_ELEMS;
    } else if ((size_t)out_size == WC_ELEMS) {
        wc = (float*)d_out;
        cudaGetSymbolAddress(&sym, g_scratch_amap);
        amap = (float*)sym;
    } else {
        cudaGetSymbolAddress(&sym, g_scratch_wc);
        wc = (float*)sym;
        amap = (float*)d_out;
    }

    const int SMEM_K3 = (32 * 1025) * sizeof(float);

    cudaFuncSetAttribute(k1_mma,
                         cudaFuncAttributeMaxDynamicSharedMemorySize, K1_SMEM_BYTES);
    cudaFuncSetAttribute(k3_softmax_l,
                         cudaFuncAttributeMaxDynamicSharedMemorySize, SMEM_K3);

    k1_mma<<<dim3(LL / 64, BB), 512, K1_SMEM_BYTES>>>(query, ctx);
    k3_softmax_l<<<dim3(QQ / 32, BB), 1024, SMEM_K3>>>(amap);
    k4_mma<<<dim3(4, BB), 256>>>(ctx, amap, wc);
}

// round 10
// speedup vs baseline: 1.3382x; 1.3245x over previous
#include <cuda_runtime.h>
#include <cuda_bf16.h>
#include <cstdint>
#include <math.h>

#define BB 128
#define DD 128
#define QQ 256
#define LL 1024
#define TEMP 4.0f

#define QUERY_ELEMS ((size_t)BB * DD * QQ)
#define WC_ELEMS    ((size_t)BB * DD * QQ)
#define AMAP_ELEMS  ((size_t)BB * QQ * LL)

__device__ __align__(16) float g_attn_q[(size_t)BB * LL * QQ];
__device__ __align__(16) float g_scratch_amap[AMAP_ELEMS];
__device__ __align__(16) float g_scratch_wc[WC_ELEMS];

// ============================ helpers ======================================
__device__ __forceinline__ uint32_t smem_u32(const void* p) {
    uint32_t a;
    asm("{ .reg .u64 t; cvta.to.shared.u64 t, %1; cvt.u32.u64 %0, t; }"
        : "=r"(a) : "l"(p));
    return a;
}
__device__ __forceinline__ uint32_t pack2bf(float x, float y) {
    __nv_bfloat162 h = __floats2bfloat162_rn(x, y);
    return *(uint32_t*)&h;
}
__device__ __forceinline__ void split2(float x, float y,
                                       uint32_t& hi, uint32_t& lo) {
    __nv_bfloat16 hx = __float2bfloat16_rn(x);
    __nv_bfloat16 hy = __float2bfloat16_rn(y);
    float rx = x - __bfloat162float(hx);
    float ry = y - __bfloat162float(hy);
    __nv_bfloat162 h2; h2.x = hx; h2.y = hy;
    hi = *(uint32_t*)&h2;
    lo = pack2bf(rx, ry);
}
#define LDMATRIX_X4(r0, r1, r2, r3, addr) \
    asm volatile("ldmatrix.sync.aligned.m8n8.x4.shared.b16 {%0,%1,%2,%3}, [%4];" \
                 : "=r"(r0), "=r"(r1), "=r"(r2), "=r"(r3) : "r"(addr))
#define LDMATRIX_X4_T(r0, r1, r2, r3, addr) \
    asm volatile("ldmatrix.sync.aligned.m8n8.x4.trans.shared.b16 {%0,%1,%2,%3}, [%4];" \
                 : "=r"(r0), "=r"(r1), "=r"(r2), "=r"(r3) : "r"(addr))
#define MMA_BF16(c, a0, a1, a2, a3, b0, b1) \
    asm volatile("mma.sync.aligned.m16n8k16.row.col.f32.bf16.bf16.f32 " \
                 "{%0,%1,%2,%3}, {%4,%5,%6,%7}, {%8,%9}, {%0,%1,%2,%3};" \
                 : "+f"((c)[0]), "+f"((c)[1]), "+f"((c)[2]), "+f"((c)[3]) \
                 : "r"(a0), "r"(a1), "r"(a2), "r"(a3), "r"(b0), "r"(b1))

// ---------------------------------------------------------------------------
// Kernel 1 v3: natural d-major tiles + ldmatrix.trans (no software transpose).
// CTA 64(l) x 256(q), K=128 resident, 512 threads, 16 warps = 2m x 8n.
// A_s[d][l]: 128 rows x 144B; B_s[d][q]: 128 rows x 528B (both hi+lo copies).
// smem = 172,032 B; epilogue reuses it as scores[64][260] fp32.
// ---------------------------------------------------------------------------
#define K1_AHI 0
#define K1_ALO 18432
#define K1_BHI 36864
#define K1_BLO 104448
#define K1_SMEM_BYTES 172032

__global__ __launch_bounds__(512, 1)
void k1_mma(const float* __restrict__ query,
            const float* __restrict__ ctx) {
    extern __shared__ __align__(16) char smc[];
    const uint32_t sb = smem_u32(smc);

    const int tid  = threadIdx.x;
    const int lane = tid & 31;
    const int wid  = tid >> 5;       // 0..15
    const int wm   = wid & 1;        // 32 l-rows
    const int wn   = wid >> 1;       // 32 q-cols

    const int b  = blockIdx.y;
    const int l0 = blockIdx.x * 64;

    const float* ctxb = ctx + (size_t)b * DD * LL;
    const float* qb   = query + (size_t)b * DD * QQ;

    // ---- fill A: 128 d x 64 l, natural layout, conflict-free STS.64 ----
    #pragma unroll
    for (int t = 0; t < 4; t++) {
        int u  = t * 512 + tid;
        int fl = u & 15;             // float4 col along l
        int d  = u >> 4;             // 0..127
        float4 v = *(const float4*)(ctxb + (size_t)d * LL + l0 + fl * 4);
        uint32_t h0, o0, h1, o1;
        split2(v.x, v.y, h0, o0);
        split2(v.z, v.w, h1, o1);
        char* p = smc + K1_AHI + d * 144 + fl * 8;
        *(uint2*)p = make_uint2(h0, h1);
        *(uint2*)(p + (K1_ALO - K1_AHI)) = make_uint2(o0, o1);
    }
    // ---- fill B: 128 d x 256 q ----
    #pragma unroll
    for (int t = 0; t < 16; t++) {
        int u  = t * 512 + tid;
        int fq = u & 63;
        int d  = u >> 6;
        float4 v = *(const float4*)(qb + (size_t)d * QQ + fq * 4);
        uint32_t h0, o0, h1, o1;
        split2(v.x, v.y, h0, o0);
        split2(v.z, v.w, h1, o1);
        char* p = smc + K1_BHI + d * 528 + fq * 8;
        *(uint2*)p = make_uint2(h0, h1);
        *(uint2*)(p + (K1_BLO - K1_BHI)) = make_uint2(o0, o1);
    }
    __syncthreads();

    float acc[2][4][4];
    #pragma unroll
    for (int i = 0; i < 2; i++)
        #pragma unroll
        for (int j = 0; j < 4; j++)
            #pragma unroll
            for (int k = 0; k < 4; k++) acc[i][j][k] = 0.0f;

    const int krA = ((lane >> 4) << 3) + (lane & 7);          // + ks*16
    const int mcs = (((lane >> 3) & 1) << 3);                  // m sub-col
    const int krB = (((lane >> 3) & 1) << 3) + (lane & 7);
    const int ncs = ((lane >> 4) << 3);                        // n sub-col

    for (int ks = 0; ks < 8; ks++) {
        uint32_t ah[2][4], al[2][4];
        #pragma unroll
        for (int mt = 0; mt < 2; mt++) {
            int mcol = wm * 32 + mt * 16 + mcs;
            uint32_t ad = sb + K1_AHI + (uint32_t)(ks * 16 + krA) * 144 + mcol * 2;
            LDMATRIX_X4_T(ah[mt][0], ah[mt][1], ah[mt][2], ah[mt][3], ad);
            LDMATRIX_X4_T(al[mt][0], al[mt][1], al[mt][2], al[mt][3],
                          ad + (K1_ALO - K1_AHI));
        }
        #pragma unroll
        for (int j = 0; j < 2; j++) {
            int ncol = wn * 32 + j * 16 + ncs;
            uint32_t bd = sb + K1_BHI + (uint32_t)(ks * 16 + krB) * 528 + ncol * 2;
            uint32_t bh0, bh1, bh2, bh3, bl0, bl1, bl2, bl3;
            LDMATRIX_X4_T(bh0, bh1, bh2, bh3, bd);
            LDMATRIX_X4_T(bl0, bl1, bl2, bl3, bd + (K1_BLO - K1_BHI));
            #pragma unroll
            for (int mt = 0; mt < 2; mt++) {
                MMA_BF16(acc[mt][j * 2],     ah[mt][0], ah[mt][1], ah[mt][2], ah[mt][3], bh0, bh1);
                MMA_BF16(acc[mt][j * 2 + 1], ah[mt][0], ah[mt][1], ah[mt][2], ah[mt][3], bh2, bh3);
                MMA_BF16(acc[mt][j * 2],     ah[mt][0], ah[mt][1], ah[mt][2], ah[mt][3], bl0, bl1);
                MMA_BF16(acc[mt][j * 2 + 1], ah[mt][0], ah[mt][1], ah[mt][2], ah[mt][3], bl2, bl3);
                MMA_BF16(acc[mt][j * 2],     al[mt][0], al[mt][1], al[mt][2], al[mt][3], bh0, bh1);
                MMA_BF16(acc[mt][j * 2 + 1], al[mt][0], al[mt][1], al[mt][2], al[mt][3], bh2, bh3);
            }
        }
    }
    __syncthreads();   // tiles dead; reuse smem as scores

    // ---- scores: 64 rows x 260 fp32 ----
    float* sc = (float*)smc;
    const int gid = lane >> 2;
    const int tig = lane & 3;
    #pragma unroll
    for (int mt = 0; mt < 2; mt++) {
        int r0 = wm * 32 + mt * 16 + gid;
        #pragma unroll
        for (int nt = 0; nt < 4; nt++) {
            int q = wn * 32 + nt * 8 + tig * 2;
            *(float2*)(sc + (size_t)r0 * 260 + q) =
                make_float2(acc[mt][nt][0], acc[mt][nt][1]);
            *(float2*)(sc + (size_t)(r0 + 8) * 260 + q) =
                make_float2(acc[mt][nt][2], acc[mt][nt][3]);
        }
    }
    __syncthreads();

    // ---- fused softmax over Q: warp wid owns rows wid*4..+3 ----
    const size_t outb = ((size_t)b * LL + l0 + wid * 4) * QQ;
    #pragma unroll
    for (int i = 0; i < 4; i++) {
        const float* row = sc + (size_t)(wid * 4 + i) * 260;
        float e[8];
        float m = -1e30f;
        #pragma unroll
        for (int j = 0; j < 8; j++) { e[j] = row[lane + j * 32]; m = fmaxf(m, e[j]); }
        #pragma unroll
        for (int o = 16; o; o >>= 1) m = fmaxf(m, __shfl_xor_sync(0xffffffffu, m, o));
        float s = 0.0f;
        #pragma unroll
        for (int j = 0; j < 8; j++) { e[j] = __expf(e[j] - m); s += e[j]; }
        #pragma unroll
        for (int o = 16; o; o >>= 1) s += __shfl_xor_sync(0xffffffffu, s, o);
        float inv = 1.0f / s;
        #pragma unroll
        for (int j = 0; j < 8; j++)
            g_attn_q[outb + (size_t)i * QQ + lane + j * 32] = e[j] * inv;
    }
}

// ---------------------------------------------------------------------------
// Kernel 3: attn_c[b,q,l] = softmax_l(TEMP * attn_q[b,l,q]). (unchanged)
// ---------------------------------------------------------------------------
__global__ void k3_softmax_l(float* __restrict__ amap) {
    extern __shared__ float sm3[];
    const int tid  = threadIdx.x;
    const int b    = blockIdx.y;
    const int q0   = blockIdx.x * 32;
    const int w    = tid >> 5;
    const int lane = tid & 31;

    const float* src = g_attn_q + (size_t)b * LL * QQ + q0;
    #pragma unroll
    for (int i = 0; i < 32; i++) {
        int l = i * 32 + w;
        sm3[lane * 1025 + l] = src[(size_t)l * QQ + lane];
    }
    __syncthreads();

    const float* row = sm3 + w * 1025;
    float e[32];
    float mx = -1e30f;
    #pragma unroll
    for (int i = 0; i < 32; i++) {
        float v = TEMP * row[lane + 32 * i];
        e[i] = v;
        mx = fmaxf(mx, v);
    }
    #pragma unroll
    for (int o = 16; o; o >>= 1) mx = fmaxf(mx, __shfl_xor_sync(0xffffffffu, mx, o));
    float s = 0.0f;
    #pragma unroll
    for (int i = 0; i < 32; i++) { e[i] = __expf(e[i] - mx); s += e[i]; }
    #pragma unroll
    for (int o = 16; o; o >>= 1) s += __shfl_xor_sync(0xffffffffu, s, o);
    float inv = 1.0f / s;

    float* dst = amap + ((size_t)b * QQ + q0 + w) * LL;
    #pragma unroll
    for (int i = 0; i < 32; i++) dst[lane + 32 * i] = e[i] * inv;
}

// ---------------------------------------------------------------------------
// Kernel 4 (HMMA bf16 split): unchanged from R6.
// ---------------------------------------------------------------------------
#define KC    32
#define NCH   (LL / KC)
#define ROWU  20
#define AHI_O 0
#define ALO_O (64 * ROWU)
#define BHI_O (2 * 64 * ROWU)
#define BLO_O (2 * 64 * ROWU + 128 * ROWU)
#define SM4U  (2 * 64 * ROWU + 2 * 128 * ROWU)

__global__ __launch_bounds__(256)
void k4_mma(const float* __restrict__ ctx,
            const float* __restrict__ amap,
            float* __restrict__ wc) {
    __shared__ __align__(16) uint32_t sm[SM4U];
    const uint32_t sb = smem_u32(sm);

    const int tid  = threadIdx.x;
    const int lane = tid & 31;
    const int wid  = tid >> 5;
    const int wm   = wid & 1;
    const int wn   = wid >> 1;

    const int b  = blockIdx.y;
    const int d0 = (blockIdx.x & 1) * 64;
    const int q0 = (blockIdx.x >> 1) * 128;

    const float* A  = ctx  + (size_t)b * DD * LL + (size_t)d0 * LL;
    const float* Bm = amap + ((size_t)b * QQ + q0) * LL;

    float acc[2][4][4];
    #pragma unroll
    for (int i = 0; i < 2; i++)
        #pragma unroll
        for (int j = 0; j < 4; j++)
            #pragma unroll
            for (int k = 0; k < 4; k++) acc[i][j][k] = 0.0f;

    const uint32_t a_row = wm * 32 + (lane & 15);
    const uint32_t a_col = (lane >> 4) * 16;
    const uint32_t b_rowbase = wn * 32 + ((lane >> 4) << 3) + (lane & 7);
    const uint32_t b_col = ((lane >> 3) & 1) * 16;

    for (int c = 0; c < NCH; c++) {
        const int l0 = c * KC;

        #pragma unroll
        for (int t = 0; t < 2; t++) {
            int idx = t * 256 + tid;
            int row = idx >> 3;
            int f   = idx & 7;
            float4 v = *(const float4*)(A + (size_t)row * LL + l0 + f * 4);
            uint32_t h0, l0p, h1, l1p;
            split2(v.x, v.y, h0, l0p);
            split2(v.z, v.w, h1, l1p);
            int o = row * ROWU + f * 2;
            sm[AHI_O + o] = h0; sm[AHI_O + o + 1] = h1;
            sm[ALO_O + o] = l0p; sm[ALO_O + o + 1] = l1p;
        }
        #pragma unroll
        for (int t = 0; t < 4; t++) {
            int idx = t * 256 + tid;
            int row = idx >> 3;
            int f   = idx & 7;
            float4 v = *(const float4*)(Bm + (size_t)row * LL + l0 + f * 4);
            uint32_t h0, l0p, h1, l1p;
            split2(v.x, v.y, h0, l0p);
            split2(v.z, v.w, h1, l1p);
            int o = row * ROWU + f * 2;
            sm[BHI_O + o] = h0; sm[BHI_O + o + 1] = h1;
            sm[BLO_O + o] = l0p; sm[BLO_O + o + 1] = l1p;
        }
        __syncthreads();

        #pragma unroll
        for (int ks = 0; ks < 2; ks++) {
            const uint32_t kbyte = ks * 32;
            uint32_t ah[2][4], al[2][4];
            #pragma unroll
            for (int mt = 0; mt < 2; mt++) {
                uint32_t addr = sb + 4 * (AHI_O + (a_row + mt * 16) * ROWU)
                              + kbyte + a_col;
                LDMATRIX_X4(ah[mt][0], ah[mt][1], ah[mt][2], ah[mt][3], addr);
                addr += 4 * (ALO_O - AHI_O);
                LDMATRIX_X4(al[mt][0], al[mt][1], al[mt][2], al[mt][3], addr);
            }
            uint32_t bh[4][2], bl[4][2];
            #pragma unroll
            for (int p = 0; p < 2; p++) {
                uint32_t addr = sb + 4 * (BHI_O + (b_rowbase + p * 16) * ROWU)
                              + kbyte + b_col;
                LDMATRIX_X4(bh[p * 2][0], bh[p * 2][1],
                            bh[p * 2 + 1][0], bh[p * 2 + 1][1], addr);
                addr += 4 * (BLO_O - BHI_O);
                LDMATRIX_X4(bl[p * 2][0], bl[p * 2][1],
                            bl[p * 2 + 1][0], bl[p * 2 + 1][1], addr);
            }
            #pragma unroll
            for (int mt = 0; mt < 2; mt++)
                #pragma unroll
                for (int nt = 0; nt < 4; nt++)
                    MMA_BF16(acc[mt][nt], ah[mt][0], ah[mt][1], ah[mt][2],
                             ah[mt][3], bh[nt][0], bh[nt][1]);
            #pragma unroll
            for (int mt = 0; mt < 2; mt++)
                #pragma unroll
                for (int nt = 0; nt < 4; nt++)
                    MMA_BF16(acc[mt][nt], ah[mt][0], ah[mt][1], ah[mt][2],
                             ah[mt][3], bl[nt][0], bl[nt][1]);
            #pragma unroll
            for (int mt = 0; mt < 2; mt++)
                #pragma unroll
                for (int nt = 0; nt < 4; nt++)
                    MMA_BF16(acc[mt][nt], al[mt][0], al[mt][1], al[mt][2],
                             al[mt][3], bh[nt][0], bh[nt][1]);
        }
        __syncthreads();
    }

    float* outb = wc + (size_t)b * DD * QQ;
    const int gid = lane >> 2;
    const int tig = lane & 3;
    #pragma unroll
    for (int mt = 0; mt < 2; mt++) {
        #pragma unroll
        for (int nt = 0; nt < 4; nt++) {
            int d = d0 + wm * 32 + mt * 16 + gid;
            int q = q0 + wn * 32 + nt * 8 + tig * 2;
            *(float2*)(outb + (size_t)d * QQ + q) =
                make_float2(acc[mt][nt][0], acc[mt][nt][1]);
            *(float2*)(outb + (size_t)(d + 8) * QQ + q) =
                make_float2(acc[mt][nt][2], acc[mt][nt][3]);
        }
    }
}

// ---------------------------------------------------------------------------
extern "C" void kernel_launch(void* const* d_in, const int* in_sizes, int n_in,
                              void* d_out, int out_size) {
    const float* query;
    const float* ctx;
    if ((size_t)in_sizes[0] == QUERY_ELEMS) {
        query = (const float*)d_in[0];
        ctx   = (const float*)d_in[1];
    } else {
        query = (const float*)d_in[1];
        ctx   = (const float*)d_in[0];
    }

    float* wc;
    float* amap;
    void* sym;
    if ((size_t)out_size >= WC_ELEMS + AMAP_ELEMS) {
        wc   = (float*)d_out;
        amap = (float*)d_out + WC_ELEMS;
    } else if ((size_t)out_size == WC_ELEMS) {
        wc = (float*)d_out;
        cudaGetSymbolAddress(&sym, g_scratch_amap);
        amap = (float*)sym;
    } else {
        cudaGetSymbolAddress(&sym, g_scratch_wc);
        wc = (float*)sym;
        amap = (float*)d_out;
    }

    const int SMEM_K3 = (32 * 1025) * sizeof(float);

    cudaFuncSetAttribute(k1_mma,
                         cudaFuncAttributeMaxDynamicSharedMemorySize, K1_SMEM_BYTES);
    cudaFuncSetAttribute(k3_softmax_l,
                         cudaFuncAttributeMaxDynamicSharedMemorySize, SMEM_K3);

    k1_mma<<<dim3(LL / 64, BB), 512, K1_SMEM_BYTES>>>(query, ctx);
    k3_softmax_l<<<dim3(QQ / 32, BB), 1024, SMEM_K3>>>(amap);
    k4_mma<<<dim3(4, BB), 256>>>(ctx, amap, wc);
}

// round 12
// speedup vs baseline: 1.5756x; 1.1774x over previous
#include <cuda_runtime.h>
#include <cuda_bf16.h>
#include <cstdint>
#include <math.h>

#define BB 128
#define DD 128
#define QQ 256
#define LL 1024
#define TEMP 4.0f

#define QUERY_ELEMS ((size_t)BB * DD * QQ)
#define WC_ELEMS    ((size_t)BB * DD * QQ)
#define AMAP_ELEMS  ((size_t)BB * QQ * LL)

__device__ __align__(16) float g_attn_q[(size_t)BB * LL * QQ];
__device__ __align__(16) float g_scratch_amap[AMAP_ELEMS];
__device__ __align__(16) float g_scratch_wc[WC_ELEMS];

// ============================ helpers ======================================
__device__ __forceinline__ uint32_t smem_u32(const void* p) {
    uint32_t a;
    asm("{ .reg .u64 t; cvta.to.shared.u64 t, %1; cvt.u32.u64 %0, t; }"
        : "=r"(a) : "l"(p));
    return a;
}
__device__ __forceinline__ uint32_t pack2bf(float x, float y) {
    __nv_bfloat162 h = __floats2bfloat162_rn(x, y);
    return *(uint32_t*)&h;
}
__device__ __forceinline__ void split2(float x, float y,
                                       uint32_t& hi, uint32_t& lo) {
    __nv_bfloat16 hx = __float2bfloat16_rn(x);
    __nv_bfloat16 hy = __float2bfloat16_rn(y);
    float rx = x - __bfloat162float(hx);
    float ry = y - __bfloat162float(hy);
    __nv_bfloat162 h2; h2.x = hx; h2.y = hy;
    hi = *(uint32_t*)&h2;
    lo = pack2bf(rx, ry);
}
#define LDMATRIX_X4(r0, r1, r2, r3, addr) \
    asm volatile("ldmatrix.sync.aligned.m8n8.x4.shared.b16 {%0,%1,%2,%3}, [%4];" \
                 : "=r"(r0), "=r"(r1), "=r"(r2), "=r"(r3) : "r"(addr))
#define LDMATRIX_X4_T(r0, r1, r2, r3, addr) \
    asm volatile("ldmatrix.sync.aligned.m8n8.x4.trans.shared.b16 {%0,%1,%2,%3}, [%4];" \
                 : "=r"(r0), "=r"(r1), "=r"(r2), "=r"(r3) : "r"(addr))
#define MMA_BF16(c, a0, a1, a2, a3, b0, b1) \
    asm volatile("mma.sync.aligned.m16n8k16.row.col.f32.bf16.bf16.f32 " \
                 "{%0,%1,%2,%3}, {%4,%5,%6,%7}, {%8,%9}, {%0,%1,%2,%3};" \
                 : "+f"((c)[0]), "+f"((c)[1]), "+f"((c)[2]), "+f"((c)[3]) \
                 : "r"(a0), "r"(a1), "r"(a2), "r"(a3), "r"(b0), "r"(b1))

// ---------------------------------------------------------------------------
// Kernel 1 v3: natural d-major tiles + ldmatrix.trans (unchanged from R10).
// ---------------------------------------------------------------------------
#define K1_AHI 0
#define K1_ALO 18432
#define K1_BHI 36864
#define K1_BLO 104448
#define K1_SMEM_BYTES 172032

__global__ __launch_bounds__(512, 1)
void k1_mma(const float* __restrict__ query,
            const float* __restrict__ ctx) {
    extern __shared__ __align__(16) char smc[];
    const uint32_t sb = smem_u32(smc);

    const int tid  = threadIdx.x;
    const int lane = tid & 31;
    const int wid  = tid >> 5;
    const int wm   = wid & 1;
    const int wn   = wid >> 1;

    const int b  = blockIdx.y;
    const int l0 = blockIdx.x * 64;

    const float* ctxb = ctx + (size_t)b * DD * LL;
    const float* qb   = query + (size_t)b * DD * QQ;

    #pragma unroll
    for (int t = 0; t < 4; t++) {
        int u  = t * 512 + tid;
        int fl = u & 15;
        int d  = u >> 4;
        float4 v = *(const float4*)(ctxb + (size_t)d * LL + l0 + fl * 4);
        uint32_t h0, o0, h1, o1;
        split2(v.x, v.y, h0, o0);
        split2(v.z, v.w, h1, o1);
        char* p = smc + K1_AHI + d * 144 + fl * 8;
        *(uint2*)p = make_uint2(h0, h1);
        *(uint2*)(p + (K1_ALO - K1_AHI)) = make_uint2(o0, o1);
    }
    #pragma unroll
    for (int t = 0; t < 16; t++) {
        int u  = t * 512 + tid;
        int fq = u & 63;
        int d  = u >> 6;
        float4 v = *(const float4*)(qb + (size_t)d * QQ + fq * 4);
        uint32_t h0, o0, h1, o1;
        split2(v.x, v.y, h0, o0);
        split2(v.z, v.w, h1, o1);
        char* p = smc + K1_BHI + d * 528 + fq * 8;
        *(uint2*)p = make_uint2(h0, h1);
        *(uint2*)(p + (K1_BLO - K1_BHI)) = make_uint2(o0, o1);
    }
    __syncthreads();

    float acc[2][4][4];
    #pragma unroll
    for (int i = 0; i < 2; i++)
        #pragma unroll
        for (int j = 0; j < 4; j++)
            #pragma unroll
            for (int k = 0; k < 4; k++) acc[i][j][k] = 0.0f;

    const int krA = ((lane >> 4) << 3) + (lane & 7);
    const int mcs = (((lane >> 3) & 1) << 3);
    const int krB = (((lane >> 3) & 1) << 3) + (lane & 7);
    const int ncs = ((lane >> 4) << 3);

    for (int ks = 0; ks < 8; ks++) {
        uint32_t ah[2][4], al[2][4];
        #pragma unroll
        for (int mt = 0; mt < 2; mt++) {
            int mcol = wm * 32 + mt * 16 + mcs;
            uint32_t ad = sb + K1_AHI + (uint32_t)(ks * 16 + krA) * 144 + mcol * 2;
            LDMATRIX_X4_T(ah[mt][0], ah[mt][1], ah[mt][2], ah[mt][3], ad);
            LDMATRIX_X4_T(al[mt][0], al[mt][1], al[mt][2], al[mt][3],
                          ad + (K1_ALO - K1_AHI));
        }
        #pragma unroll
        for (int j = 0; j < 2; j++) {
            int ncol = wn * 32 + j * 16 + ncs;
            uint32_t bd = sb + K1_BHI + (uint32_t)(ks * 16 + krB) * 528 + ncol * 2;
            uint32_t bh0, bh1, bh2, bh3, bl0, bl1, bl2, bl3;
            LDMATRIX_X4_T(bh0, bh1, bh2, bh3, bd);
            LDMATRIX_X4_T(bl0, bl1, bl2, bl3, bd + (K1_BLO - K1_BHI));
            #pragma unroll
            for (int mt = 0; mt < 2; mt++) {
                MMA_BF16(acc[mt][j * 2],     ah[mt][0], ah[mt][1], ah[mt][2], ah[mt][3], bh0, bh1);
                MMA_BF16(acc[mt][j * 2 + 1], ah[mt][0], ah[mt][1], ah[mt][2], ah[mt][3], bh2, bh3);
                MMA_BF16(acc[mt][j * 2],     ah[mt][0], ah[mt][1], ah[mt][2], ah[mt][3], bl0, bl1);
                MMA_BF16(acc[mt][j * 2 + 1], ah[mt][0], ah[mt][1], ah[mt][2], ah[mt][3], bl2, bl3);
                MMA_BF16(acc[mt][j * 2],     al[mt][0], al[mt][1], al[mt][2], al[mt][3], bh0, bh1);
                MMA_BF16(acc[mt][j * 2 + 1], al[mt][0], al[mt][1], al[mt][2], al[mt][3], bh2, bh3);
            }
        }
    }
    __syncthreads();

    float* sc = (float*)smc;
    const int gid = lane >> 2;
    const int tig = lane & 3;
    #pragma unroll
    for (int mt = 0; mt < 2; mt++) {
        int r0 = wm * 32 + mt * 16 + gid;
        #pragma unroll
        for (int nt = 0; nt < 4; nt++) {
            int q = wn * 32 + nt * 8 + tig * 2;
            *(float2*)(sc + (size_t)r0 * 260 + q) =
                make_float2(acc[mt][nt][0], acc[mt][nt][1]);
            *(float2*)(sc + (size_t)(r0 + 8) * 260 + q) =
                make_float2(acc[mt][nt][2], acc[mt][nt][3]);
        }
    }
    __syncthreads();

    const size_t outb = ((size_t)b * LL + l0 + wid * 4) * QQ;
    #pragma unroll
    for (int i = 0; i < 4; i++) {
        const float* row = sc + (size_t)(wid * 4 + i) * 260;
        float e[8];
        float m = -1e30f;
        #pragma unroll
        for (int j = 0; j < 8; j++) { e[j] = row[lane + j * 32]; m = fmaxf(m, e[j]); }
        #pragma unroll
        for (int o = 16; o; o >>= 1) m = fmaxf(m, __shfl_xor_sync(0xffffffffu, m, o));
        float s = 0.0f;
        #pragma unroll
        for (int j = 0; j < 8; j++) { e[j] = __expf(e[j] - m); s += e[j]; }
        #pragma unroll
        for (int o = 16; o; o >>= 1) s += __shfl_xor_sync(0xffffffffu, s, o);
        float inv = 1.0f / s;
        #pragma unroll
        for (int j = 0; j < 8; j++)
            g_attn_q[outb + (size_t)i * QQ + lane + j * 32] = e[j] * inv;
    }
}

// ---------------------------------------------------------------------------
// Kernel 3: attn_c[b,q,l] = softmax_l(TEMP * attn_q[b,l,q]). (unchanged)
// ---------------------------------------------------------------------------
__global__ void k3_softmax_l(float* __restrict__ amap) {
    extern __shared__ float sm3[];
    const int tid  = threadIdx.x;
    const int b    = blockIdx.y;
    const int q0   = blockIdx.x * 32;
    const int w    = tid >> 5;
    const int lane = tid & 31;

    const float* src = g_attn_q + (size_t)b * LL * QQ + q0;
    #pragma unroll
    for (int i = 0; i < 32; i++) {
        int l = i * 32 + w;
        sm3[lane * 1025 + l] = src[(size_t)l * QQ + lane];
    }
    __syncthreads();

    const float* row = sm3 + w * 1025;
    float e[32];
    float mx = -1e30f;
    #pragma unroll
    for (int i = 0; i < 32; i++) {
        float v = TEMP * row[lane + 32 * i];
        e[i] = v;
        mx = fmaxf(mx, v);
    }
    #pragma unroll
    for (int o = 16; o; o >>= 1) mx = fmaxf(mx, __shfl_xor_sync(0xffffffffu, mx, o));
    float s = 0.0f;
    #pragma unroll
    for (int i = 0; i < 32; i++) { e[i] = __expf(e[i] - mx); s += e[i]; }
    #pragma unroll
    for (int o = 16; o; o >>= 1) s += __shfl_xor_sync(0xffffffffu, s, o);
    float inv = 1.0f / s;

    float* dst = amap + ((size_t)b * QQ + q0 + w) * LL;
    #pragma unroll
    for (int i = 0; i < 32; i++) dst[lane + 32 * i] = e[i] * inv;
}

// ---------------------------------------------------------------------------
// Kernel 4 v2 (HMMA bf16 split, double-buffered, FIXED lo-offset):
//   wc[b,d,q] = sum_l ctx[b,d,l] * attn_c[b,q,l].
// CTA 64d x 128q, K=1024 chunked by 32. grid (4,B), 256 threads, 2 CTA/SM.
// ---------------------------------------------------------------------------
#define KC    32
#define NCH   (LL / KC)
#define ROWU  20
#define AHI_O 0
#define ALO_O (64 * ROWU)                    // A lo delta = 1280
#define BHI_O (2 * 64 * ROWU)
#define BLO_O (2 * 64 * ROWU + 128 * ROWU)   // B lo delta = 2560
#define K4_STAGE_U 7680
#define K4_SMEM_BYTES (2 * K4_STAGE_U * 4)   // 61440 B

__global__ __launch_bounds__(256, 2)
void k4_mma(const float* __restrict__ ctx,
            const float* __restrict__ amap,
            float* __restrict__ wc) {
    extern __shared__ __align__(16) uint32_t sm4[];
    const uint32_t sb = smem_u32(sm4);

    const int tid  = threadIdx.x;
    const int lane = tid & 31;
    const int wid  = tid >> 5;
    const int wm   = wid & 1;
    const int wn   = wid >> 1;

    const int b  = blockIdx.y;
    const int d0 = (blockIdx.x & 1) * 64;
    const int q0 = (blockIdx.x >> 1) * 128;

    const float* A  = ctx  + (size_t)b * DD * LL + (size_t)d0 * LL;
    const float* Bm = amap + ((size_t)b * QQ + q0) * LL;

    const int frow = tid >> 3;       // 0..31
    const int ff   = tid & 7;

    float4 pa0, pa1, pb0, pb1, pb2, pb3;

#define K4_LD(c) do { \
        const int _l0 = (c) * KC; \
        pa0 = *(const float4*)(A  + (size_t)(frow)      * LL + _l0 + ff * 4); \
        pa1 = *(const float4*)(A  + (size_t)(frow + 32) * LL + _l0 + ff * 4); \
        pb0 = *(const float4*)(Bm + (size_t)(frow)      * LL + _l0 + ff * 4); \
        pb1 = *(const float4*)(Bm + (size_t)(frow + 32) * LL + _l0 + ff * 4); \
        pb2 = *(const float4*)(Bm + (size_t)(frow + 64) * LL + _l0 + ff * 4); \
        pb3 = *(const float4*)(Bm + (size_t)(frow + 96) * LL + _l0 + ff * 4); \
    } while (0)

// lo_delta: u32 offset from hi region to matching lo region (A:1280, B:2560)
#define K4_ST1(v, base, row, lo_delta) do { \
        uint32_t _h0, _o0, _h1, _o1; \
        split2((v).x, (v).y, _h0, _o0); \
        split2((v).z, (v).w, _h1, _o1); \
        uint32_t* _p = stp + (base) + (row) * ROWU + ff * 2; \
        _p[0] = _h0; _p[1] = _h1; \
        _p[(lo_delta)] = _o0; _p[(lo_delta) + 1] = _o1; \
    } while (0)

#define K4_ST(s) do { \
        uint32_t* stp = sm4 + (s) * K4_STAGE_U; \
        K4_ST1(pa0, AHI_O, frow,       (ALO_O - AHI_O)); \
        K4_ST1(pa1, AHI_O, frow + 32,  (ALO_O - AHI_O)); \
        K4_ST1(pb0, BHI_O, frow,       (BLO_O - BHI_O)); \
        K4_ST1(pb1, BHI_O, frow + 32,  (BLO_O - BHI_O)); \
        K4_ST1(pb2, BHI_O, frow + 64,  (BLO_O - BHI_O)); \
        K4_ST1(pb3, BHI_O, frow + 96,  (BLO_O - BHI_O)); \
    } while (0)

    float acc[2][4][4];
    #pragma unroll
    for (int i = 0; i < 2; i++)
        #pragma unroll
        for (int j = 0; j < 4; j++)
            #pragma unroll
            for (int k = 0; k < 4; k++) acc[i][j][k] = 0.0f;

    const uint32_t a_row = wm * 32 + (lane & 15);
    const uint32_t a_col = (lane >> 4) * 16;
    const uint32_t b_rowbase = wn * 32 + ((lane >> 4) << 3) + (lane & 7);
    const uint32_t b_col = ((lane >> 3) & 1) * 16;

    K4_LD(0);
    K4_ST(0);
    __syncthreads();

    for (int c = 0; c < NCH; c++) {
        if (c < NCH - 1) K4_LD(c + 1);

        const uint32_t stage_b = sb + (uint32_t)(c & 1) * (K4_STAGE_U * 4);
        #pragma unroll
        for (int ks = 0; ks < 2; ks++) {
            const uint32_t kbyte = ks * 32;
            uint32_t ah[2][4], al[2][4];
            #pragma unroll
            for (int mt = 0; mt < 2; mt++) {
                uint32_t addr = stage_b + 4 * (AHI_O + (a_row + mt * 16) * ROWU)
                              + kbyte + a_col;
                LDMATRIX_X4(ah[mt][0], ah[mt][1], ah[mt][2], ah[mt][3], addr);
                addr += 4 * (ALO_O - AHI_O);
                LDMATRIX_X4(al[mt][0], al[mt][1], al[mt][2], al[mt][3], addr);
            }
            uint32_t bh[4][2], bl[4][2];
            #pragma unroll
            for (int p = 0; p < 2; p++) {
                uint32_t addr = stage_b + 4 * (BHI_O + (b_rowbase + p * 16) * ROWU)
                              + kbyte + b_col;
                LDMATRIX_X4(bh[p * 2][0], bh[p * 2][1],
                            bh[p * 2 + 1][0], bh[p * 2 + 1][1], addr);
                addr += 4 * (BLO_O - BHI_O);
                LDMATRIX_X4(bl[p * 2][0], bl[p * 2][1],
                            bl[p * 2 + 1][0], bl[p * 2 + 1][1], addr);
            }
            #pragma unroll
            for (int mt = 0; mt < 2; mt++)
                #pragma unroll
                for (int nt = 0; nt < 4; nt++)
                    MMA_BF16(acc[mt][nt], ah[mt][0], ah[mt][1], ah[mt][2],
                             ah[mt][3], bh[nt][0], bh[nt][1]);
            #pragma unroll
            for (int mt = 0; mt < 2; mt++)
                #pragma unroll
                for (int nt = 0; nt < 4; nt++)
                    MMA_BF16(acc[mt][nt], ah[mt][0], ah[mt][1], ah[mt][2],
                             ah[mt][3], bl[nt][0], bl[nt][1]);
            #pragma unroll
            for (int mt = 0; mt < 2; mt++)
                #pragma unroll
                for (int nt = 0; nt < 4; nt++)
                    MMA_BF16(acc[mt][nt], al[mt][0], al[mt][1], al[mt][2],
                             al[mt][3], bh[nt][0], bh[nt][1]);
        }

        if (c < NCH - 1) K4_ST((c + 1) & 1);
        __syncthreads();
    }

    float* outb = wc + (size_t)b * DD * QQ;
    const int gid = lane >> 2;
    const int tig = lane & 3;
    #pragma unroll
    for (int mt = 0; mt < 2; mt++) {
        #pragma unroll
        for (int nt = 0; nt < 4; nt++) {
            int d = d0 + wm * 32 + mt * 16 + gid;
            int q = q0 + wn * 32 + nt * 8 + tig * 2;
            *(float2*)(outb + (size_t)d * QQ + q) =
                make_float2(acc[mt][nt][0], acc[mt][nt][1]);
            *(float2*)(outb + (size_t)(d + 8) * QQ + q) =
                make_float2(acc[mt][nt][2], acc[mt][nt][3]);
        }
    }
}

// ---------------------------------------------------------------------------
extern "C" void kernel_launch(void* const* d_in, const int* in_sizes, int n_in,
                              void* d_out, int out_size) {
    const float* query;
    const float* ctx;
    if ((size_t)in_sizes[0] == QUERY_ELEMS) {
        query = (const float*)d_in[0];
        ctx   = (const float*)d_in[1];
    } else {
        query = (const float*)d_in[1];
        ctx   = (const float*)d_in[0];
    }

    float* wc;
    float* amap;
    void* sym;
    if ((size_t)out_size >= WC_ELEMS + AMAP_ELEMS) {
        wc   = (float*)d_out;
        amap = (float*)d_out + WC_ELEMS;
    } else if ((size_t)out_size == WC_ELEMS) {
        wc = (float*)d_out;
        cudaGetSymbolAddress(&sym, g_scratch_amap);
        amap = (float*)sym;
    } else {
        cudaGetSymbolAddress(&sym, g_scratch_wc);
        wc = (float*)sym;
        amap = (float*)d_out;
    }

    const int SMEM_K3 = (32 * 1025) * sizeof(float);

    cudaFuncSetAttribute(k1_mma,
                         cudaFuncAttributeMaxDynamicSharedMemorySize, K1_SMEM_BYTES);
    cudaFuncSetAttribute(k3_softmax_l,
                         cudaFuncAttributeMaxDynamicSharedMemorySize, SMEM_K3);
    cudaFuncSetAttribute(k4_mma,
                         cudaFuncAttributeMaxDynamicSharedMemorySize, K4_SMEM_BYTES);

    k1_mma<<<dim3(LL / 64, BB), 512, K1_SMEM_BYTES>>>(query, ctx);
    k3_softmax_l<<<dim3(QQ / 32, BB), 1024, SMEM_K3>>>(amap);
    k4_mma<<<dim3(4, BB), 256, K4_SMEM_BYTES>>>(ctx, amap, wc);
}

// round 13
// speedup vs baseline: 1.5888x; 1.0084x over previous
#include <cuda_runtime.h>
#include <cuda_bf16.h>
#include <cstdint>
#include <math.h>

#define BB 128
#define DD 128
#define QQ 256
#define LL 1024
#define TEMP 4.0f

#define QUERY_ELEMS ((size_t)BB * DD * QQ)
#define WC_ELEMS    ((size_t)BB * DD * QQ)
#define AMAP_ELEMS  ((size_t)BB * QQ * LL)

__device__ __align__(16) float g_attn_q[(size_t)BB * LL * QQ];
__device__ __align__(16) float g_scratch_amap[AMAP_ELEMS];
__device__ __align__(16) float g_scratch_wc[WC_ELEMS];

// ============================ helpers ======================================
__device__ __forceinline__ uint32_t smem_u32(const void* p) {
    uint32_t a;
    asm("{ .reg .u64 t; cvta.to.shared.u64 t, %1; cvt.u32.u64 %0, t; }"
        : "=r"(a) : "l"(p));
    return a;
}
__device__ __forceinline__ uint32_t pack2bf(float x, float y) {
    __nv_bfloat162 h = __floats2bfloat162_rn(x, y);
    return *(uint32_t*)&h;
}
__device__ __forceinline__ void split2(float x, float y,
                                       uint32_t& hi, uint32_t& lo) {
    __nv_bfloat16 hx = __float2bfloat16_rn(x);
    __nv_bfloat16 hy = __float2bfloat16_rn(y);
    float rx = x - __bfloat162float(hx);
    float ry = y - __bfloat162float(hy);
    __nv_bfloat162 h2; h2.x = hx; h2.y = hy;
    hi = *(uint32_t*)&h2;
    lo = pack2bf(rx, ry);
}
#define LDMATRIX_X4(r0, r1, r2, r3, addr) \
    asm volatile("ldmatrix.sync.aligned.m8n8.x4.shared.b16 {%0,%1,%2,%3}, [%4];" \
                 : "=r"(r0), "=r"(r1), "=r"(r2), "=r"(r3) : "r"(addr))
#define LDMATRIX_X4_T(r0, r1, r2, r3, addr) \
    asm volatile("ldmatrix.sync.aligned.m8n8.x4.trans.shared.b16 {%0,%1,%2,%3}, [%4];" \
                 : "=r"(r0), "=r"(r1), "=r"(r2), "=r"(r3) : "r"(addr))
#define MMA_BF16(c, a0, a1, a2, a3, b0, b1) \
    asm volatile("mma.sync.aligned.m16n8k16.row.col.f32.bf16.bf16.f32 " \
                 "{%0,%1,%2,%3}, {%4,%5,%6,%7}, {%8,%9}, {%0,%1,%2,%3};" \
                 : "+f"((c)[0]), "+f"((c)[1]), "+f"((c)[2]), "+f"((c)[3]) \
                 : "r"(a0), "r"(a1), "r"(a2), "r"(a3), "r"(b0), "r"(b1))

// ---------------------------------------------------------------------------
// Kernel 1 v4 (chunked + double-buffered): scores = ctx^T @ query, fused
// softmax over Q. CTA 64(l) x 256(q), K=128(d) chunked by 32, 512 threads.
// Stage (u32): AHI[32x36] ALO[32x36] BHI[32x132] BLO[32x132] = 10752 u32.
// Two stages = 86016 B; epilogue reuses smem as scores[64][260] (66560 B).
// ---------------------------------------------------------------------------
#define K1C_AHI 0
#define K1C_ALO 1152
#define K1C_BHI 2304
#define K1C_BLO 6528
#define K1_STAGE_U 10752
#define K1_SMEM_BYTES (2 * K1_STAGE_U * 4)   // 86016 B

__global__ __launch_bounds__(512, 1)
void k1_mma(const float* __restrict__ query,
            const float* __restrict__ ctx) {
    extern __shared__ __align__(16) char smc[];
    uint32_t* smu = (uint32_t*)smc;
    const uint32_t sb = smem_u32(smc);

    const int tid  = threadIdx.x;
    const int lane = tid & 31;
    const int wid  = tid >> 5;
    const int wm   = wid & 1;
    const int wn   = wid >> 1;

    const int b  = blockIdx.y;
    const int l0 = blockIdx.x * 64;

    const float* ctxb = ctx + (size_t)b * DD * LL;
    const float* qb   = query + (size_t)b * DD * QQ;

    // fill indices (constant per thread)
    const int a_fl = tid & 15;       // float4 col along l (0..15)
    const int a_dr = tid >> 4;       // d-row within chunk (0..31)
    const int b_fq = tid & 63;       // float4 col along q (0..63)
    const int b_dr = tid >> 6;       // d-row base (0..7), +8 steps

    float4 pa, pb0, pb1, pb2, pb3;

#define K1_LD(c) do { \
        const int _d0 = (c) * 32; \
        pa  = *(const float4*)(ctxb + (size_t)(_d0 + a_dr) * LL + l0 + a_fl * 4); \
        pb0 = *(const float4*)(qb + (size_t)(_d0 + b_dr)      * QQ + b_fq * 4); \
        pb1 = *(const float4*)(qb + (size_t)(_d0 + b_dr +  8) * QQ + b_fq * 4); \
        pb2 = *(const float4*)(qb + (size_t)(_d0 + b_dr + 16) * QQ + b_fq * 4); \
        pb3 = *(const float4*)(qb + (size_t)(_d0 + b_dr + 24) * QQ + b_fq * 4); \
    } while (0)

#define K1_ST1(v, base, row, stride_u, lo_delta, col) do { \
        uint32_t _h0, _o0, _h1, _o1; \
        split2((v).x, (v).y, _h0, _o0); \
        split2((v).z, (v).w, _h1, _o1); \
        uint32_t* _p = stp + (base) + (row) * (stride_u) + (col) * 2; \
        _p[0] = _h0; _p[1] = _h1; \
        _p[(lo_delta)] = _o0; _p[(lo_delta) + 1] = _o1; \
    } while (0)

#define K1_ST(s) do { \
        uint32_t* stp = smu + (s) * K1_STAGE_U; \
        K1_ST1(pa,  K1C_AHI, a_dr,      36,  (K1C_ALO - K1C_AHI), a_fl); \
        K1_ST1(pb0, K1C_BHI, b_dr,      132, (K1C_BLO - K1C_BHI), b_fq); \
        K1_ST1(pb1, K1C_BHI, b_dr + 8,  132, (K1C_BLO - K1C_BHI), b_fq); \
        K1_ST1(pb2, K1C_BHI, b_dr + 16, 132, (K1C_BLO - K1C_BHI), b_fq); \
        K1_ST1(pb3, K1C_BHI, b_dr + 24, 132, (K1C_BLO - K1C_BHI), b_fq); \
    } while (0)

    float acc[2][4][4];
    #pragma unroll
    for (int i = 0; i < 2; i++)
        #pragma unroll
        for (int j = 0; j < 4; j++)
            #pragma unroll
            for (int k = 0; k < 4; k++) acc[i][j][k] = 0.0f;

    const int krA = ((lane >> 4) << 3) + (lane & 7);
    const int mcs = (((lane >> 3) & 1) << 3);
    const int krB = (((lane >> 3) & 1) << 3) + (lane & 7);
    const int ncs = ((lane >> 4) << 3);

    K1_LD(0);
    K1_ST(0);
    __syncthreads();

    for (int c = 0; c < 4; c++) {
        if (c < 3) K1_LD(c + 1);

        const uint32_t stage_b = sb + (uint32_t)(c & 1) * (K1_STAGE_U * 4);
        #pragma unroll
        for (int ks = 0; ks < 2; ks++) {
            uint32_t ah[2][4], al[2][4];
            #pragma unroll
            for (int mt = 0; mt < 2; mt++) {
                int mcol = wm * 32 + mt * 16 + mcs;
                uint32_t ad = stage_b + K1C_AHI * 4
                            + (uint32_t)(ks * 16 + krA) * 144 + mcol * 2;
                LDMATRIX_X4_T(ah[mt][0], ah[mt][1], ah[mt][2], ah[mt][3], ad);
                LDMATRIX_X4_T(al[mt][0], al[mt][1], al[mt][2], al[mt][3],
                              ad + (K1C_ALO - K1C_AHI) * 4);
            }
            #pragma unroll
            for (int j = 0; j < 2; j++) {
                int ncol = wn * 32 + j * 16 + ncs;
                uint32_t bd = stage_b + K1C_BHI * 4
                            + (uint32_t)(ks * 16 + krB) * 528 + ncol * 2;
                uint32_t bh0, bh1, bh2, bh3, bl0, bl1, bl2, bl3;
                LDMATRIX_X4_T(bh0, bh1, bh2, bh3, bd);
                LDMATRIX_X4_T(bl0, bl1, bl2, bl3, bd + (K1C_BLO - K1C_BHI) * 4);
                #pragma unroll
                for (int mt = 0; mt < 2; mt++) {
                    MMA_BF16(acc[mt][j * 2],     ah[mt][0], ah[mt][1], ah[mt][2], ah[mt][3], bh0, bh1);
                    MMA_BF16(acc[mt][j * 2 + 1], ah[mt][0], ah[mt][1], ah[mt][2], ah[mt][3], bh2, bh3);
                    MMA_BF16(acc[mt][j * 2],     ah[mt][0], ah[mt][1], ah[mt][2], ah[mt][3], bl0, bl1);
                    MMA_BF16(acc[mt][j * 2 + 1], ah[mt][0], ah[mt][1], ah[mt][2], ah[mt][3], bl2, bl3);
                    MMA_BF16(acc[mt][j * 2],     al[mt][0], al[mt][1], al[mt][2], al[mt][3], bh0, bh1);
                    MMA_BF16(acc[mt][j * 2 + 1], al[mt][0], al[mt][1], al[mt][2], al[mt][3], bh2, bh3);
                }
            }
        }

        if (c < 3) K1_ST((c + 1) & 1);
        __syncthreads();
    }

    // ---- scores: 64 rows x 260 fp32 (reuses stage smem) ----
    float* sc = (float*)smc;
    const int gid = lane >> 2;
    const int tig = lane & 3;
    #pragma unroll
    for (int mt = 0; mt < 2; mt++) {
        int r0 = wm * 32 + mt * 16 + gid;
        #pragma unroll
        for (int nt = 0; nt < 4; nt++) {
            int q = wn * 32 + nt * 8 + tig * 2;
            *(float2*)(sc + (size_t)r0 * 260 + q) =
                make_float2(acc[mt][nt][0], acc[mt][nt][1]);
            *(float2*)(sc + (size_t)(r0 + 8) * 260 + q) =
                make_float2(acc[mt][nt][2], acc[mt][nt][3]);
        }
    }
    __syncthreads();

    const size_t outb = ((size_t)b * LL + l0 + wid * 4) * QQ;
    #pragma unroll
    for (int i = 0; i < 4; i++) {
        const float* row = sc + (size_t)(wid * 4 + i) * 260;
        float e[8];
        float m = -1e30f;
        #pragma unroll
        for (int j = 0; j < 8; j++) { e[j] = row[lane + j * 32]; m = fmaxf(m, e[j]); }
        #pragma unroll
        for (int o = 16; o; o >>= 1) m = fmaxf(m, __shfl_xor_sync(0xffffffffu, m, o));
        float s = 0.0f;
        #pragma unroll
        for (int j = 0; j < 8; j++) { e[j] = __expf(e[j] - m); s += e[j]; }
        #pragma unroll
        for (int o = 16; o; o >>= 1) s += __shfl_xor_sync(0xffffffffu, s, o);
        float inv = 1.0f / s;
        #pragma unroll
        for (int j = 0; j < 8; j++)
            g_attn_q[outb + (size_t)i * QQ + lane + j * 32] = e[j] * inv;
    }
}

// ---------------------------------------------------------------------------
// Kernel 3: attn_c[b,q,l] = softmax_l(TEMP * attn_q[b,l,q]). (unchanged)
// ---------------------------------------------------------------------------
__global__ void k3_softmax_l(float* __restrict__ amap) {
    extern __shared__ float sm3[];
    const int tid  = threadIdx.x;
    const int b    = blockIdx.y;
    const int q0   = blockIdx.x * 32;
    const int w    = tid >> 5;
    const int lane = tid & 31;

    const float* src = g_attn_q + (size_t)b * LL * QQ + q0;
    #pragma unroll
    for (int i = 0; i < 32; i++) {
        int l = i * 32 + w;
        sm3[lane * 1025 + l] = src[(size_t)l * QQ + lane];
    }
    __syncthreads();

    const float* row = sm3 + w * 1025;
    float e[32];
    float mx = -1e30f;
    #pragma unroll
    for (int i = 0; i < 32; i++) {
        float v = TEMP * row[lane + 32 * i];
        e[i] = v;
        mx = fmaxf(mx, v);
    }
    #pragma unroll
    for (int o = 16; o; o >>= 1) mx = fmaxf(mx, __shfl_xor_sync(0xffffffffu, mx, o));
    float s = 0.0f;
    #pragma unroll
    for (int i = 0; i < 32; i++) { e[i] = __expf(e[i] - mx); s += e[i]; }
    #pragma unroll
    for (int o = 16; o; o >>= 1) s += __shfl_xor_sync(0xffffffffu, s, o);
    float inv = 1.0f / s;

    float* dst = amap + ((size_t)b * QQ + q0 + w) * LL;
    #pragma unroll
    for (int i = 0; i < 32; i++) dst[lane + 32 * i] = e[i] * inv;
}

// ---------------------------------------------------------------------------
// Kernel 4 v2 (HMMA bf16 split, double-buffered): unchanged from R12.
// ---------------------------------------------------------------------------
#define KC    32
#define NCH   (LL / KC)
#define ROWU  20
#define AHI_O 0
#define ALO_O (64 * ROWU)
#define BHI_O (2 * 64 * ROWU)
#define BLO_O (2 * 64 * ROWU + 128 * ROWU)
#define K4_STAGE_U 7680
#define K4_SMEM_BYTES (2 * K4_STAGE_U * 4)

__global__ __launch_bounds__(256, 2)
void k4_mma(const float* __restrict__ ctx,
            const float* __restrict__ amap,
            float* __restrict__ wc) {
    extern __shared__ __align__(16) uint32_t sm4[];
    const uint32_t sb = smem_u32(sm4);

    const int tid  = threadIdx.x;
    const int lane = tid & 31;
    const int wid  = tid >> 5;
    const int wm   = wid & 1;
    const int wn   = wid >> 1;

    const int b  = blockIdx.y;
    const int d0 = (blockIdx.x & 1) * 64;
    const int q0 = (blockIdx.x >> 1) * 128;

    const float* A  = ctx  + (size_t)b * DD * LL + (size_t)d0 * LL;
    const float* Bm = amap + ((size_t)b * QQ + q0) * LL;

    const int frow = tid >> 3;
    const int ff   = tid & 7;

    float4 pa0, pa1, pb0, pb1, pb2, pb3;

#define K4_LD(c) do { \
        const int _l0 = (c) * KC; \
        pa0 = *(const float4*)(A  + (size_t)(frow)      * LL + _l0 + ff * 4); \
        pa1 = *(const float4*)(A  + (size_t)(frow + 32) * LL + _l0 + ff * 4); \
        pb0 = *(const float4*)(Bm + (size_t)(frow)      * LL + _l0 + ff * 4); \
        pb1 = *(const float4*)(Bm + (size_t)(frow + 32) * LL + _l0 + ff * 4); \
        pb2 = *(const float4*)(Bm + (size_t)(frow + 64) * LL + _l0 + ff * 4); \
        pb3 = *(const float4*)(Bm + (size_t)(frow + 96) * LL + _l0 + ff * 4); \
    } while (0)

#define K4_ST1(v, base, row, lo_delta) do { \
        uint32_t _h0, _o0, _h1, _o1; \
        split2((v).x, (v).y, _h0, _o0); \
        split2((v).z, (v).w, _h1, _o1); \
        uint32_t* _p = stp + (base) + (row) * ROWU + ff * 2; \
        _p[0] = _h0; _p[1] = _h1; \
        _p[(lo_delta)] = _o0; _p[(lo_delta) + 1] = _o1; \
    } while (0)

#define K4_ST(s) do { \
        uint32_t* stp = sm4 + (s) * K4_STAGE_U; \
        K4_ST1(pa0, AHI_O, frow,       (ALO_O - AHI_O)); \
        K4_ST1(pa1, AHI_O, frow + 32,  (ALO_O - AHI_O)); \
        K4_ST1(pb0, BHI_O, frow,       (BLO_O - BHI_O)); \
        K4_ST1(pb1, BHI_O, frow + 32,  (BLO_O - BHI_O)); \
        K4_ST1(pb2, BHI_O, frow + 64,  (BLO_O - BHI_O)); \
        K4_ST1(pb3, BHI_O, frow + 96,  (BLO_O - BHI_O)); \
    } while (0)

    float acc[2][4][4];
    #pragma unroll
    for (int i = 0; i < 2; i++)
        #pragma unroll
        for (int j = 0; j < 4; j++)
            #pragma unroll
            for (int k = 0; k < 4; k++) acc[i][j][k] = 0.0f;

    const uint32_t a_row = wm * 32 + (lane & 15);
    const uint32_t a_col = (lane >> 4) * 16;
    const uint32_t b_rowbase = wn * 32 + ((lane >> 4) << 3) + (lane & 7);
    const uint32_t b_col = ((lane >> 3) & 1) * 16;

    K4_LD(0);
    K4_ST(0);
    __syncthreads();

    for (int c = 0; c < NCH; c++) {
        if (c < NCH - 1) K4_LD(c + 1);

        const uint32_t stage_b = sb + (uint32_t)(c & 1) * (K4_STAGE_U * 4);
        #pragma unroll
        for (int ks = 0; ks < 2; ks++) {
            const uint32_t kbyte = ks * 32;
            uint32_t ah[2][4], al[2][4];
            #pragma unroll
            for (int mt = 0; mt < 2; mt++) {
                uint32_t addr = stage_b + 4 * (AHI_O + (a_row + mt * 16) * ROWU)
                              + kbyte + a_col;
                LDMATRIX_X4(ah[mt][0], ah[mt][1], ah[mt][2], ah[mt][3], addr);
                addr += 4 * (ALO_O - AHI_O);
                LDMATRIX_X4(al[mt][0], al[mt][1], al[mt][2], al[mt][3], addr);
            }
            uint32_t bh[4][2], bl[4][2];
            #pragma unroll
            for (int p = 0; p < 2; p++) {
                uint32_t addr = stage_b + 4 * (BHI_O + (b_rowbase + p * 16) * ROWU)
                              + kbyte + b_col;
                LDMATRIX_X4(bh[p * 2][0], bh[p * 2][1],
                            bh[p * 2 + 1][0], bh[p * 2 + 1][1], addr);
                addr += 4 * (BLO_O - BHI_O);
                LDMATRIX_X4(bl[p * 2][0], bl[p * 2][1],
                            bl[p * 2 + 1][0], bl[p * 2 + 1][1], addr);
            }
            #pragma unroll
            for (int mt = 0; mt < 2; mt++)
                #pragma unroll
                for (int nt = 0; nt < 4; nt++)
                    MMA_BF16(acc[mt][nt], ah[mt][0], ah[mt][1], ah[mt][2],
                             ah[mt][3], bh[nt][0], bh[nt][1]);
            #pragma unroll
            for (int mt = 0; mt < 2; mt++)
                #pragma unroll
                for (int nt = 0; nt < 4; nt++)
                    MMA_BF16(acc[mt][nt], ah[mt][0], ah[mt][1], ah[mt][2],
                             ah[mt][3], bl[nt][0], bl[nt][1]);
            #pragma unroll
            for (int mt = 0; mt < 2; mt++)
                #pragma unroll
                for (int nt = 0; nt < 4; nt++)
                    MMA_BF16(acc[mt][nt], al[mt][0], al[mt][1], al[mt][2],
                             al[mt][3], bh[nt][0], bh[nt][1]);
        }

        if (c < NCH - 1) K4_ST((c + 1) & 1);
        __syncthreads();
    }

    float* outb = wc + (size_t)b * DD * QQ;
    const int gid = lane >> 2;
    const int tig = lane & 3;
    #pragma unroll
    for (int mt = 0; mt < 2; mt++) {
        #pragma unroll
        for (int nt = 0; nt < 4; nt++) {
            int d = d0 + wm * 32 + mt * 16 + gid;
            int q = q0 + wn * 32 + nt * 8 + tig * 2;
            *(float2*)(outb + (size_t)d * QQ + q) =
                make_float2(acc[mt][nt][0], acc[mt][nt][1]);
            *(float2*)(outb + (size_t)(d + 8) * QQ + q) =
                make_float2(acc[mt][nt][2], acc[mt][nt][3]);
        }
    }
}

// ---------------------------------------------------------------------------
extern "C" void kernel_launch(void* const* d_in, const int* in_sizes, int n_in,
                              void* d_out, int out_size) {
    const float* query;
    const float* ctx;
    if ((size_t)in_sizes[0] == QUERY_ELEMS) {
        query = (const float*)d_in[0];
        ctx   = (const float*)d_in[1];
    } else {
        query = (const float*)d_in[1];
        ctx   = (const float*)d_in[0];
    }

    float* wc;
    float* amap;
    void* sym;
    if ((size_t)out_size >= WC_ELEMS + AMAP_ELEMS) {
        wc   = (float*)d_out;
        amap = (float*)d_out + WC_ELEMS;
    } else if ((size_t)out_size == WC_ELEMS) {
        wc = (float*)d_out;
        cudaGetSymbolAddress(&sym, g_scratch_amap);
        amap = (float*)sym;
    } else {
        cudaGetSymbolAddress(&sym, g_scratch_wc);
        wc = (float*)sym;
        amap = (float*)d_out;
    }

    const int SMEM_K3 = (32 * 1025) * sizeof(float);

    cudaFuncSetAttribute(k1_mma,
                         cudaFuncAttributeMaxDynamicSharedMemorySize, K1_SMEM_BYTES);
    cudaFuncSetAttribute(k3_softmax_l,
                         cudaFuncAttributeMaxDynamicSharedMemorySize, SMEM_K3);
    cudaFuncSetAttribute(k4_mma,
                         cudaFuncAttributeMaxDynamicSharedMemorySize, K4_SMEM_BYTES);

    k1_mma<<<dim3(LL / 64, BB), 512, K1_SMEM_BYTES>>>(query, ctx);
    k3_softmax_l<<<dim3(QQ / 32, BB), 1024, SMEM_K3>>>(amap);
    k4_mma<<<dim3(4, BB), 256, K4_SMEM_BYTES>>>(ctx, amap, wc);
}